// round 3
// baseline (speedup 1.0000x reference)
#include <cuda_runtime.h>
#include <math.h>

// ---------------- static device scratch (no allocations allowed) -------------
__device__ float    g_A1[2048u*2048u];
__device__ float    g_A2[1024u*1024u];
__device__ float    g_A3[512u*512u];
__device__ float    g_Ra[1024u*2048u];
__device__ unsigned g_bits[2048u*128u];
__device__ float    g_h0[4096*64];
__device__ float    g_h1[2048*64];
__device__ float    g_h2[1024*64];
__device__ float    g_h3[512*64];
__device__ float    g_hp[2048*64];
__device__ float    g_ys[4096*64];
__device__ float    g_u [4096*64];
__device__ float    g_dinv0[4096];
__device__ float    g_dinv1[2048];
__device__ float    g_dinv2[1024];
__device__ float    g_dinv3[512];
__device__ int      g_perm0[2048];
__device__ int      g_perm1[1024];
__device__ int      g_perm2[512];
__device__ float    g_vals[2048];
__device__ float    g_score[4096];
__device__ float    g_invpnorm;

// ---------------- dinv[i] = 1/sqrt(rowsum(A)+2) ------------------------------
__global__ void k_dinv(const float* __restrict__ A, int n, float* __restrict__ dinv) {
    int row = blockIdx.x;
    const float* a = A + (size_t)row * n;
    float s = 0.f;
    for (int j = threadIdx.x; j < n; j += blockDim.x) s += a[j];
    for (int o = 16; o; o >>= 1) s += __shfl_xor_sync(0xffffffffu, s, o);
    __shared__ float red[8];
    int lane = threadIdx.x & 31, warp = threadIdx.x >> 5;
    if (lane == 0) red[warp] = s;
    __syncthreads();
    if (threadIdx.x == 0) {
        float t = 0.f;
        #pragma unroll
        for (int w = 0; w < 8; w++) t += red[w];
        dinv[row] = 1.0f / sqrtf(t + 2.0f);
    }
}

// ---------------- ys = dinv .* (X @ W)  (X: n x 64, W: 64 x 64) --------------
__global__ void k_featw(const float* __restrict__ X, const float* __restrict__ W,
                        const float* __restrict__ dinv, float* __restrict__ ys, int n) {
    __shared__ float Ws[64][64];
    __shared__ float Xs[64][65];
    int tid = threadIdx.x;            // 256 threads
    int rowb = blockIdx.x * 64;
    const float4* W4 = (const float4*)W;
    float4* Ws4 = (float4*)&Ws[0][0];
    for (int i = tid; i < 1024; i += 256) Ws4[i] = W4[i];
    const float4* X4 = (const float4*)(X + (size_t)rowb * 64);
    for (int i = tid; i < 1024; i += 256) {
        float4 v = X4[i];
        int r = i >> 4, c = (i & 15) * 4;
        Xs[r][c] = v.x; Xs[r][c+1] = v.y; Xs[r][c+2] = v.z; Xs[r][c+3] = v.w;
    }
    __syncthreads();
    int r  = tid >> 2;                // 64 rows
    int cg = (tid & 3) * 16;          // 16 cols per thread
    float acc[16];
    #pragma unroll
    for (int c = 0; c < 16; c++) acc[c] = 0.f;
    for (int k = 0; k < 64; k++) {
        float a = Xs[r][k];
        #pragma unroll
        for (int c = 0; c < 16; c++) acc[c] += a * Ws[k][cg + c];
    }
    float d = dinv[rowb + r];
    float* dst = ys + (size_t)(rowb + r) * 64 + cg;
    #pragma unroll
    for (int c = 0; c < 16; c++) dst[c] = d * acc[c];
}

// ------- h = act( dinv_i*(A@ys)_i + 2*dinv_i*ys_i + b )  (A: n x n) ----------
__global__ void k_prop(const float* __restrict__ A, const float* __restrict__ ys,
                       const float* __restrict__ dinv, const float* __restrict__ bias,
                       float* __restrict__ hout, int n, int relu) {
    __shared__ float sA[32][33];
    __shared__ float sB[32][64];
    int tid = threadIdx.x;            // 256
    int tx = tid & 15, ty = tid >> 4;
    int rowb = blockIdx.x * 32;
    float acc[2][4] = {{0.f,0.f,0.f,0.f},{0.f,0.f,0.f,0.f}};
    for (int kb = 0; kb < n; kb += 32) {
        {   // A tile 32x32 (256 float4)
            int r = tid >> 3, c4 = (tid & 7) * 4;
            float4 v = *(const float4*)(A + (size_t)(rowb + r) * n + kb + c4);
            sA[r][c4] = v.x; sA[r][c4+1] = v.y; sA[r][c4+2] = v.z; sA[r][c4+3] = v.w;
        }
        {   // ys tile 32x64 (512 float4)
            for (int q = tid; q < 512; q += 256) {
                int r = q >> 4, c4 = (q & 15) * 4;
                *(float4*)&sB[r][c4] = *(const float4*)(ys + (size_t)(kb + r) * 64 + c4);
            }
        }
        __syncthreads();
        #pragma unroll
        for (int kk = 0; kk < 32; kk++) {
            float a0 = sA[ty*2+0][kk];
            float a1 = sA[ty*2+1][kk];
            float4 b = *(float4*)&sB[kk][tx*4];
            acc[0][0] += a0*b.x; acc[0][1] += a0*b.y; acc[0][2] += a0*b.z; acc[0][3] += a0*b.w;
            acc[1][0] += a1*b.x; acc[1][1] += a1*b.y; acc[1][2] += a1*b.z; acc[1][3] += a1*b.w;
        }
        __syncthreads();
    }
    #pragma unroll
    for (int i = 0; i < 2; i++) {
        int r = rowb + ty*2 + i;
        float d = dinv[r];
        #pragma unroll
        for (int j = 0; j < 4; j++) {
            int c = tx*4 + j;
            float v = d*acc[i][j] + 2.f*d*ys[(size_t)r*64 + c] + bias[c];
            if (relu) v = fmaxf(v, 0.f);
            hout[(size_t)r*64 + c] = v;
        }
    }
}

// ---------------- scores ------------------------------------------------------
__global__ void k_invpnorm(const float* __restrict__ p) {
    int l = threadIdx.x; // 32
    float v = p[l]*p[l] + p[l+32]*p[l+32];
    for (int o = 16; o; o >>= 1) v += __shfl_xor_sync(0xffffffffu, v, o);
    if (l == 0) g_invpnorm = 1.0f / sqrtf(v);
}

__global__ void k_score(const float* __restrict__ h, const float* __restrict__ p,
                        float* __restrict__ score, int n) {
    int gw = (blockIdx.x * blockDim.x + threadIdx.x) >> 5;
    int lane = threadIdx.x & 31;
    if (gw >= n) return;
    float d = h[(size_t)gw*64 + lane] * p[lane] + h[(size_t)gw*64 + 32 + lane] * p[32 + lane];
    for (int o = 16; o; o >>= 1) d += __shfl_xor_sync(0xffffffffu, d, o);
    if (lane == 0) score[gw] = tanhf(d * g_invpnorm);
}

// --------- top-k via single-block bitonic sort (score desc, idx asc) ---------
__global__ void k_topk(const float* __restrict__ score, int n, int k,
                       int* __restrict__ perm, float* __restrict__ vals) {
    __shared__ float ss[4096];
    __shared__ int   si[4096];
    int t = threadIdx.x; // 1024
    for (int i = t; i < n; i += blockDim.x) { ss[i] = score[i]; si[i] = i; }
    __syncthreads();
    for (int kk = 2; kk <= n; kk <<= 1) {
        for (int j = kk >> 1; j > 0; j >>= 1) {
            for (int i = t; i < n; i += blockDim.x) {
                int ixj = i ^ j;
                if (ixj > i) {
                    float s1 = ss[i], s2 = ss[ixj];
                    int   i1 = si[i], i2 = si[ixj];
                    bool b21 = (s2 > s1) || (s2 == s1 && i2 < i1); // e2 before e1
                    bool dir = ((i & kk) == 0);
                    bool sw  = dir ? b21 : !b21;
                    if (sw) { ss[i] = s2; ss[ixj] = s1; si[i] = i2; si[ixj] = i1; }
                }
            }
            __syncthreads();
        }
    }
    for (int i = t; i < k; i += blockDim.x) { perm[i] = si[i]; vals[i] = ss[i]; }
}

// ---------------- pooled feature gather: hp[a] = h[perm[a]] * vals[a] --------
__global__ void k_gather_h(const float* __restrict__ h, const int* __restrict__ perm,
                           const float* __restrict__ vals, float* __restrict__ hp, int k) {
    int idx = blockIdx.x * blockDim.x + threadIdx.x;
    if (idx >= k * 64) return;
    int a = idx >> 6, f = idx & 63;
    hp[idx] = h[(size_t)perm[a]*64 + f] * vals[a];
}

// ---------------- bit-pack selected rows of (adj + I) ------------------------
__global__ void k_pack(const float* __restrict__ adj, const int* __restrict__ perm,
                       unsigned* __restrict__ bits, int n) {
    int a  = blockIdx.x;
    int pa = perm[a];
    const float* row = adj + (size_t)pa * n;
    int lane = threadIdx.x & 31;
    int warp = threadIdx.x >> 5;        // 4 warps
    int W = n >> 5;
    for (int w = warp; w < W; w += 4) {
        int j = w*32 + lane;
        bool v = (row[j] != 0.f) || (j == pa);
        unsigned m = __ballot_sync(0xffffffffu, v);
        if (lane == 0) bits[(size_t)a * W + w] = m;
    }
}

// ---------------- A_next[a][b] = popc-dot, diag zeroed -----------------------
__global__ void k_popcmm(const unsigned* __restrict__ bits, float* __restrict__ C,
                         int k, int W) {
    __shared__ unsigned sA[64][33], sB[64][33];
    int tid = threadIdx.x, tx = tid & 15, ty = tid >> 4;
    int rb = blockIdx.x * 64, cb = blockIdx.y * 64;
    int acc[4][4];
    #pragma unroll
    for (int i = 0; i < 4; i++)
        #pragma unroll
        for (int j = 0; j < 4; j++) acc[i][j] = 0;
    for (int wb = 0; wb < W; wb += 32) {
        for (int q = tid; q < 512; q += 256) {
            int r = q >> 3, c4 = (q & 7) * 4;
            uint4 v = *(const uint4*)(bits + (size_t)(rb + r) * W + wb + c4);
            sA[r][c4] = v.x; sA[r][c4+1] = v.y; sA[r][c4+2] = v.z; sA[r][c4+3] = v.w;
            uint4 u = *(const uint4*)(bits + (size_t)(cb + r) * W + wb + c4);
            sB[r][c4] = u.x; sB[r][c4+1] = u.y; sB[r][c4+2] = u.z; sB[r][c4+3] = u.w;
        }
        __syncthreads();
        #pragma unroll
        for (int w = 0; w < 32; w++) {
            unsigned a0 = sA[ty*4+0][w], a1 = sA[ty*4+1][w], a2 = sA[ty*4+2][w], a3 = sA[ty*4+3][w];
            unsigned b0 = sB[tx*4+0][w], b1 = sB[tx*4+1][w], b2 = sB[tx*4+2][w], b3 = sB[tx*4+3][w];
            acc[0][0] += __popc(a0&b0); acc[0][1] += __popc(a0&b1); acc[0][2] += __popc(a0&b2); acc[0][3] += __popc(a0&b3);
            acc[1][0] += __popc(a1&b0); acc[1][1] += __popc(a1&b1); acc[1][2] += __popc(a1&b2); acc[1][3] += __popc(a1&b3);
            acc[2][0] += __popc(a2&b0); acc[2][1] += __popc(a2&b1); acc[2][2] += __popc(a2&b2); acc[2][3] += __popc(a2&b3);
            acc[3][0] += __popc(a3&b0); acc[3][1] += __popc(a3&b1); acc[3][2] += __popc(a3&b2); acc[3][3] += __popc(a3&b3);
        }
        __syncthreads();
    }
    #pragma unroll
    for (int i = 0; i < 4; i++) {
        int gr = rb + ty*4 + i;
        #pragma unroll
        for (int j = 0; j < 4; j++) {
            int gc = cb + tx*4 + j;
            C[(size_t)gr * k + gc] = (gr == gc) ? 0.f : (float)acc[i][j];
        }
    }
}

// ---------------- Ra[a][j] = A[perm[a]][j] + (j == perm[a]) ------------------
__global__ void k_gather_ra(const float* __restrict__ A, const int* __restrict__ perm,
                            float* __restrict__ Ra, int k, int m) {
    int idx = blockIdx.x * blockDim.x + threadIdx.x;
    if (idx >= k * m) return;
    int a = idx / m, j = idx - a * m;
    int pa = perm[a];
    float v = A[(size_t)pa * m + j];
    if (j == pa) v += 1.f;
    Ra[idx] = v;
}

// ---------------- C = Ra @ Ra^T (k x k, inner m), diag zeroed ----------------
__global__ void k_ramm(const float* __restrict__ Ra, float* __restrict__ C, int k, int m) {
    __shared__ float sA[64][33], sB[64][33];
    int tid = threadIdx.x, tx = tid & 15, ty = tid >> 4;
    int rb = blockIdx.x * 64, cb = blockIdx.y * 64;
    float acc[4][4];
    #pragma unroll
    for (int i = 0; i < 4; i++)
        #pragma unroll
        for (int j = 0; j < 4; j++) acc[i][j] = 0.f;
    for (int kb = 0; kb < m; kb += 32) {
        for (int q = tid; q < 512; q += 256) {
            int r = q >> 3, c4 = (q & 7) * 4;
            float4 v = *(const float4*)(Ra + (size_t)(rb + r) * m + kb + c4);
            sA[r][c4] = v.x; sA[r][c4+1] = v.y; sA[r][c4+2] = v.z; sA[r][c4+3] = v.w;
            float4 u = *(const float4*)(Ra + (size_t)(cb + r) * m + kb + c4);
            sB[r][c4] = u.x; sB[r][c4+1] = u.y; sB[r][c4+2] = u.z; sB[r][c4+3] = u.w;
        }
        __syncthreads();
        #pragma unroll
        for (int w = 0; w < 32; w++) {
            float a0 = sA[ty*4+0][w], a1 = sA[ty*4+1][w], a2 = sA[ty*4+2][w], a3 = sA[ty*4+3][w];
            float b0 = sB[tx*4+0][w], b1 = sB[tx*4+1][w], b2 = sB[tx*4+2][w], b3 = sB[tx*4+3][w];
            acc[0][0] += a0*b0; acc[0][1] += a0*b1; acc[0][2] += a0*b2; acc[0][3] += a0*b3;
            acc[1][0] += a1*b0; acc[1][1] += a1*b1; acc[1][2] += a1*b2; acc[1][3] += a1*b3;
            acc[2][0] += a2*b0; acc[2][1] += a2*b1; acc[2][2] += a2*b2; acc[2][3] += a2*b3;
            acc[3][0] += a3*b0; acc[3][1] += a3*b1; acc[3][2] += a3*b2; acc[3][3] += a3*b3;
        }
        __syncthreads();
    }
    #pragma unroll
    for (int i = 0; i < 4; i++) {
        int gr = rb + ty*4 + i;
        #pragma unroll
        for (int j = 0; j < 4; j++) {
            int gc = cb + tx*4 + j;
            C[(size_t)gr * k + gc] = (gr == gc) ? 0.f : acc[i][j];
        }
    }
}

// ---------------- res[perm[a]] += hsub[a]  (perm rows distinct) --------------
__global__ void k_scatter_add(float* __restrict__ res, const int* __restrict__ perm,
                              const float* __restrict__ hsub, int k) {
    int idx = blockIdx.x * blockDim.x + threadIdx.x;
    if (idx >= k * 64) return;
    int a = idx >> 6, f = idx & 63;
    res[(size_t)perm[a]*64 + f] += hsub[idx];
}

// ---------------- out[i] = (sum_f relu(g) * fcw)/(1-prob) + fcb --------------
__global__ void k_final(const float* __restrict__ g, const float* __restrict__ fcw,
                        const float* __restrict__ fcb, const float* __restrict__ prob,
                        float* __restrict__ out, int n) {
    int gw = (blockIdx.x * blockDim.x + threadIdx.x) >> 5;
    int lane = threadIdx.x & 31;
    if (gw >= n) return;
    float v = fmaxf(g[(size_t)gw*64 + lane], 0.f)      * fcw[lane]
            + fmaxf(g[(size_t)gw*64 + 32 + lane], 0.f) * fcw[32 + lane];
    for (int o = 16; o; o >>= 1) v += __shfl_xor_sync(0xffffffffu, v, o);
    if (lane == 0) out[gw] = v / (1.f - prob[0]) + fcb[0];
}

// =============================================================================
extern "C" void kernel_launch(void* const* d_in, const int* in_sizes, int n_in,
                              void* d_out, int out_size) {
    (void)in_sizes; (void)n_in; (void)out_size;
    const float* x    = (const float*)d_in[0];
    const float* adj  = (const float*)d_in[1];
    const float* prob = (const float*)d_in[2];
    const float* dW   = (const float*)d_in[3];
    const float* db   = (const float*)d_in[4];
    const float* pw   = (const float*)d_in[5];
    const float* uW   = (const float*)d_in[6];
    const float* ub   = (const float*)d_in[7];
    const float* fcw  = (const float*)d_in[8];
    const float* fcb  = (const float*)d_in[9];
    float* out = (float*)d_out;

    float *A1, *A2, *A3, *Ra, *h0, *h1, *h2, *h3, *hp, *ys, *u;
    float *dinv0, *dinv1, *dinv2, *dinv3, *vals, *score;
    int *perm0, *perm1, *perm2;
    unsigned* bits;
    cudaGetSymbolAddress((void**)&A1, g_A1);
    cudaGetSymbolAddress((void**)&A2, g_A2);
    cudaGetSymbolAddress((void**)&A3, g_A3);
    cudaGetSymbolAddress((void**)&Ra, g_Ra);
    cudaGetSymbolAddress((void**)&bits, g_bits);
    cudaGetSymbolAddress((void**)&h0, g_h0);
    cudaGetSymbolAddress((void**)&h1, g_h1);
    cudaGetSymbolAddress((void**)&h2, g_h2);
    cudaGetSymbolAddress((void**)&h3, g_h3);
    cudaGetSymbolAddress((void**)&hp, g_hp);
    cudaGetSymbolAddress((void**)&ys, g_ys);
    cudaGetSymbolAddress((void**)&u,  g_u);
    cudaGetSymbolAddress((void**)&dinv0, g_dinv0);
    cudaGetSymbolAddress((void**)&dinv1, g_dinv1);
    cudaGetSymbolAddress((void**)&dinv2, g_dinv2);
    cudaGetSymbolAddress((void**)&dinv3, g_dinv3);
    cudaGetSymbolAddress((void**)&perm0, g_perm0);
    cudaGetSymbolAddress((void**)&perm1, g_perm1);
    cudaGetSymbolAddress((void**)&perm2, g_perm2);
    cudaGetSymbolAddress((void**)&vals, g_vals);
    cudaGetSymbolAddress((void**)&score, g_score);

    // ---------------- down level 0 (n = 4096) ----------------
    k_dinv <<<4096, 256>>>(adj, 4096, dinv0);
    k_featw<<<64,   256>>>(x, dW, dinv0, ys, 4096);
    k_prop <<<128,  256>>>(adj, ys, dinv0, db, h0, 4096, 1);

    // ---------------- pool 0: 4096 -> 2048 -------------------
    k_invpnorm<<<1, 32>>>(pw);
    k_score  <<<512, 256>>>(h0, pw, score, 4096);
    k_topk   <<<1, 1024>>>(score, 4096, 2048, perm0, vals);
    k_gather_h<<<512, 256>>>(h0, perm0, vals, hp, 2048);
    k_pack   <<<2048, 128>>>(adj, perm0, bits, 4096);
    k_popcmm <<<dim3(32, 32), 256>>>(bits, A1, 2048, 128);
    k_dinv   <<<2048, 256>>>(A1, 2048, dinv1);
    k_featw  <<<32, 256>>>(hp, dW + 1*4096, dinv1, ys, 2048);
    k_prop   <<<64, 256>>>(A1, ys, dinv1, db + 64, h1, 2048, 1);

    // ---------------- pool 1: 2048 -> 1024 -------------------
    k_invpnorm<<<1, 32>>>(pw + 64);
    k_score  <<<256, 256>>>(h1, pw + 64, score, 2048);
    k_topk   <<<1, 1024>>>(score, 2048, 1024, perm1, vals);
    k_gather_h<<<256, 256>>>(h1, perm1, vals, hp, 1024);
    k_gather_ra<<<8192, 256>>>(A1, perm1, Ra, 1024, 2048);
    k_ramm   <<<dim3(16, 16), 256>>>(Ra, A2, 1024, 2048);
    k_dinv   <<<1024, 256>>>(A2, 1024, dinv2);
    k_featw  <<<16, 256>>>(hp, dW + 2*4096, dinv2, ys, 1024);
    k_prop   <<<32, 256>>>(A2, ys, dinv2, db + 128, h2, 1024, 1);

    // ---------------- pool 2: 1024 -> 512 --------------------
    k_invpnorm<<<1, 32>>>(pw + 128);
    k_score  <<<128, 256>>>(h2, pw + 128, score, 1024);
    k_topk   <<<1, 1024>>>(score, 1024, 512, perm2, vals);
    k_gather_h<<<128, 256>>>(h2, perm2, vals, hp, 512);
    k_gather_ra<<<2048, 256>>>(A2, perm2, Ra, 512, 1024);
    k_ramm   <<<dim3(8, 8), 256>>>(Ra, A3, 512, 1024);
    k_dinv   <<<512, 256>>>(A3, 512, dinv3);
    k_featw  <<<8, 256>>>(hp, dW + 3*4096, dinv3, ys, 512);
    k_prop   <<<16, 256>>>(A3, ys, dinv3, db + 192, h3, 512, 1);

    // ---------------- up 0: scatter into h2 (1024), relu -----
    k_scatter_add<<<128, 256>>>(h2, perm2, h3, 512);
    k_featw  <<<16, 256>>>(h2, uW, dinv2, ys, 1024);
    k_prop   <<<32, 256>>>(A2, ys, dinv2, ub, u, 1024, 1);

    // ---------------- up 1: scatter into h1 (2048), relu -----
    k_scatter_add<<<256, 256>>>(h1, perm1, u, 1024);
    k_featw  <<<32, 256>>>(h1, uW + 4096, dinv1, ys, 2048);
    k_prop   <<<64, 256>>>(A1, ys, dinv1, ub + 64, u, 2048, 1);

    // ---------------- up 2: scatter into h0 (4096), no relu --
    k_scatter_add<<<512, 256>>>(h0, perm0, u, 2048);
    k_featw  <<<64, 256>>>(h0, uW + 8192, dinv0, ys, 4096);
    k_prop   <<<128, 256>>>(adj, ys, dinv0, ub + 128, u, 4096, 0);

    // ---------------- final: relu, dropout(0), fc ------------
    k_final  <<<512, 256>>>(u, fcw, fcb, prob, out, 4096);
}

// round 5
// speedup vs baseline: 1.9183x; 1.9183x over previous
#include <cuda_runtime.h>
#include <cuda_bf16.h>
#include <math.h>

// ---------------- static device scratch (no allocations allowed) -------------
__device__ float         g_A1[2048u*2048u];
__device__ float         g_A2[1024u*1024u];
__device__ float         g_A3[512u*512u];
__device__ float         g_Ra[512u*1024u];
__device__ __nv_bfloat16 g_Ra16[1024u*2048u];
__device__ float g_h0[4096*64];
__device__ float g_h1[2048*64];
__device__ float g_h2[1024*64];
__device__ float g_h3[512*64];
__device__ float g_hp[2048*64];
__device__ float g_ys[4096*64];
__device__ float g_u[4096*64];
__device__ float g_dinv0[4096];
__device__ float g_dinv1[2048];
__device__ float g_dinv2[1024];
__device__ float g_dinv3[512];
__device__ int   g_perm0[2048];
__device__ int   g_perm1[1024];
__device__ int   g_perm2[512];
__device__ float g_vals[2048];
__device__ float g_score[4096];
__device__ float g_invpnorm;
__device__ int   g_deg[4096];
__device__ int   g_offA[4097];
__device__ int   g_idxA[4096u*1024u];
__device__ float g_valA[4096u*1024u];
__device__ int   g_off1[2049];
__device__ int   g_idx1[2048u*2048u];
__device__ float g_val1[2048u*2048u];
__device__ int   g_sel[4096];

// ========================= CSR construction ==================================
__global__ void k_deg(const float* __restrict__ A, int n, int* __restrict__ deg,
                      float* __restrict__ dinvOrNull) {
    int row = blockIdx.x * 8 + (threadIdx.x >> 5);
    int lane = threadIdx.x & 31;
    const float* a = A + (size_t)row * n;
    int c = 0;
    for (int j = lane; j < n; j += 32) c += (a[j] != 0.f) ? 1 : 0;
    for (int o = 16; o; o >>= 1) c += __shfl_xor_sync(0xffffffffu, c, o);
    if (lane == 0) {
        deg[row] = c;
        if (dinvOrNull != 0) dinvOrNull[row] = 1.0f / sqrtf((float)c + 2.0f);
    }
}

__global__ void k_scan(const int* __restrict__ deg, int* __restrict__ off, int n) {
    __shared__ int s[4096];
    int t = threadIdx.x; // 1024 threads
    for (int i = t; i < n; i += 1024) s[i] = deg[i];
    __syncthreads();
    for (int d = 1; d < n; d <<= 1) {
        int v[4];
        int q = 0;
        for (int i = t; i < n; i += 1024) { v[q] = (i >= d) ? s[i - d] : 0; q++; }
        __syncthreads();
        q = 0;
        for (int i = t; i < n; i += 1024) { s[i] += v[q]; q++; }
        __syncthreads();
    }
    if (t == 0) off[0] = 0;
    for (int i = t; i < n; i += 1024) off[i + 1] = s[i];
}

__global__ void k_fill(const float* __restrict__ A, const int* __restrict__ off,
                       int* __restrict__ idx, float* __restrict__ val, int n) {
    int row = blockIdx.x * 8 + (threadIdx.x >> 5);
    int lane = threadIdx.x & 31;
    const float* a = A + (size_t)row * n;
    int ptr = off[row];
    for (int j0 = 0; j0 < n; j0 += 32) {
        float v = a[j0 + lane];
        unsigned msk = __ballot_sync(0xffffffffu, v != 0.f);
        if (v != 0.f) {
            int p = ptr + __popc(msk & ((1u << lane) - 1u));
            idx[p] = j0 + lane;
            val[p] = v;
        }
        ptr += __popc(msk);
    }
}

// ---------------- dinv[i] = 1/sqrt(rowsum(A)+2) (dense, weighted) ------------
__global__ void k_dinv(const float* __restrict__ A, int n, float* __restrict__ dinv) {
    int row = blockIdx.x;
    const float* a = A + (size_t)row * n;
    float s = 0.f;
    for (int j = threadIdx.x; j < n; j += blockDim.x) s += a[j];
    for (int o = 16; o; o >>= 1) s += __shfl_xor_sync(0xffffffffu, s, o);
    __shared__ float red[8];
    int lane = threadIdx.x & 31;
    int warp = threadIdx.x >> 5;
    if (lane == 0) red[warp] = s;
    __syncthreads();
    if (threadIdx.x == 0) {
        float t = 0.f;
        #pragma unroll
        for (int w = 0; w < 8; w++) t += red[w];
        dinv[row] = 1.0f / sqrtf(t + 2.0f);
    }
}

// ---------------- ys = dinv .* (X @ W) ---------------------------------------
__global__ void k_featw(const float* __restrict__ X, const float* __restrict__ W,
                        const float* __restrict__ dinv, float* __restrict__ ys, int n) {
    __shared__ float Ws[64][64];
    __shared__ float Xs[64][65];
    int tid = threadIdx.x; // 256
    int rowb = blockIdx.x * 64;
    const float4* W4 = (const float4*)W;
    float4* Ws4 = (float4*)&Ws[0][0];
    for (int i = tid; i < 1024; i += 256) Ws4[i] = W4[i];
    const float4* X4 = (const float4*)(X + (size_t)rowb * 64);
    for (int i = tid; i < 1024; i += 256) {
        float4 v = X4[i];
        int r = i >> 4;
        int c = (i & 15) * 4;
        Xs[r][c] = v.x; Xs[r][c+1] = v.y; Xs[r][c+2] = v.z; Xs[r][c+3] = v.w;
    }
    __syncthreads();
    int r  = tid >> 2;
    int cg = (tid & 3) * 16;
    float acc[16];
    #pragma unroll
    for (int c = 0; c < 16; c++) acc[c] = 0.f;
    for (int k = 0; k < 64; k++) {
        float a = Xs[r][k];
        #pragma unroll
        for (int c = 0; c < 16; c++) acc[c] += a * Ws[k][cg + c];
    }
    float d = dinv[rowb + r];
    float* dst = ys + (size_t)(rowb + r) * 64 + cg;
    #pragma unroll
    for (int c = 0; c < 16; c++) dst[c] = d * acc[c];
}

// ---------------- sparse prop: h = act(d*(A@ys) + 2d*ys + b) -----------------
__global__ void k_prop_sp(const int* __restrict__ off, const int* __restrict__ idx,
                          const float* __restrict__ val, const float* __restrict__ ys,
                          const float* __restrict__ dinv, const float* __restrict__ bias,
                          float* __restrict__ h, int n, int relu) {
    int row = blockIdx.x * 8 + (threadIdx.x >> 5);
    int lane = threadIdx.x & 31;
    if (row >= n) return;
    int s = off[row];
    int e = off[row + 1];
    float a0 = 0.f;
    float a1 = 0.f;
    for (int m = s; m < e; m++) {
        int j = idx[m];
        float w = val[m];
        a0 += w * ys[(size_t)j * 64 + lane];
        a1 += w * ys[(size_t)j * 64 + 32 + lane];
    }
    float d = dinv[row];
    float v0 = d * a0 + 2.f * d * ys[(size_t)row * 64 + lane] + bias[lane];
    float v1 = d * a1 + 2.f * d * ys[(size_t)row * 64 + 32 + lane] + bias[32 + lane];
    if (relu) { v0 = fmaxf(v0, 0.f); v1 = fmaxf(v1, 0.f); }
    h[(size_t)row * 64 + lane] = v0;
    h[(size_t)row * 64 + 32 + lane] = v1;
}

// ---------------- dense prop (levels 2,3) ------------------------------------
__global__ void k_prop(const float* __restrict__ A, const float* __restrict__ ys,
                       const float* __restrict__ dinv, const float* __restrict__ bias,
                       float* __restrict__ hout, int n, int relu) {
    __shared__ float sA[32][33];
    __shared__ float sB[32][64];
    int tid = threadIdx.x; // 256
    int tx = tid & 15;
    int ty = tid >> 4;
    int rowb = blockIdx.x * 32;
    float acc[2][4] = {{0.f,0.f,0.f,0.f},{0.f,0.f,0.f,0.f}};
    for (int kb = 0; kb < n; kb += 32) {
        int r0 = tid >> 3;
        int c0 = (tid & 7) * 4;
        float4 v = *(const float4*)(A + (size_t)(rowb + r0) * n + kb + c0);
        sA[r0][c0] = v.x; sA[r0][c0+1] = v.y; sA[r0][c0+2] = v.z; sA[r0][c0+3] = v.w;
        for (int q = tid; q < 512; q += 256) {
            int r = q >> 4;
            int c4 = (q & 15) * 4;
            *(float4*)&sB[r][c4] = *(const float4*)(ys + (size_t)(kb + r) * 64 + c4);
        }
        __syncthreads();
        #pragma unroll
        for (int kk = 0; kk < 32; kk++) {
            float a0 = sA[ty*2+0][kk];
            float a1 = sA[ty*2+1][kk];
            float4 b = *(float4*)&sB[kk][tx*4];
            acc[0][0] += a0*b.x; acc[0][1] += a0*b.y; acc[0][2] += a0*b.z; acc[0][3] += a0*b.w;
            acc[1][0] += a1*b.x; acc[1][1] += a1*b.y; acc[1][2] += a1*b.z; acc[1][3] += a1*b.w;
        }
        __syncthreads();
    }
    #pragma unroll
    for (int i = 0; i < 2; i++) {
        int r = rowb + ty*2 + i;
        float d = dinv[r];
        #pragma unroll
        for (int j = 0; j < 4; j++) {
            int c = tx*4 + j;
            float v = d*acc[i][j] + 2.f*d*ys[(size_t)r*64 + c] + bias[c];
            if (relu) v = fmaxf(v, 0.f);
            hout[(size_t)r*64 + c] = v;
        }
    }
}

// ---------------- scores / topk ----------------------------------------------
__global__ void k_invpnorm(const float* __restrict__ p) {
    int l = threadIdx.x; // 32
    float v = p[l]*p[l] + p[l+32]*p[l+32];
    for (int o = 16; o; o >>= 1) v += __shfl_xor_sync(0xffffffffu, v, o);
    if (l == 0) g_invpnorm = 1.0f / sqrtf(v);
}

__global__ void k_score(const float* __restrict__ h, const float* __restrict__ p,
                        float* __restrict__ score, int n) {
    int gw = (blockIdx.x * blockDim.x + threadIdx.x) >> 5;
    int lane = threadIdx.x & 31;
    if (gw >= n) return;
    float d = h[(size_t)gw*64 + lane] * p[lane] + h[(size_t)gw*64 + 32 + lane] * p[32 + lane];
    for (int o = 16; o; o >>= 1) d += __shfl_xor_sync(0xffffffffu, d, o);
    if (lane == 0) score[gw] = tanhf(d * g_invpnorm);
}

__global__ void k_topk(const float* __restrict__ score, int n, int k,
                       int* __restrict__ perm, float* __restrict__ vals) {
    __shared__ float ss[4096];
    __shared__ int   si[4096];
    int t = threadIdx.x; // 1024
    for (int i = t; i < n; i += blockDim.x) { ss[i] = score[i]; si[i] = i; }
    __syncthreads();
    for (int kk = 2; kk <= n; kk <<= 1) {
        for (int j = kk >> 1; j > 0; j >>= 1) {
            for (int i = t; i < n; i += blockDim.x) {
                int ixj = i ^ j;
                if (ixj > i) {
                    float s1 = ss[i];
                    float s2 = ss[ixj];
                    int i1 = si[i];
                    int i2 = si[ixj];
                    bool b21 = (s2 > s1) || (s2 == s1 && i2 < i1);
                    bool dir = ((i & kk) == 0);
                    bool sw = dir ? b21 : (!b21);
                    if (sw) { ss[i] = s2; ss[ixj] = s1; si[i] = i2; si[ixj] = i1; }
                }
            }
            __syncthreads();
        }
    }
    for (int i = t; i < k; i += blockDim.x) { perm[i] = si[i]; vals[i] = ss[i]; }
}

// ---------------- small utility kernels --------------------------------------
__global__ void k_gather_h(const float* __restrict__ h, const int* __restrict__ perm,
                           const float* __restrict__ vals, float* __restrict__ hp, int k) {
    int idx = blockIdx.x * blockDim.x + threadIdx.x;
    if (idx >= k * 64) return;
    int a = idx >> 6;
    int f = idx & 63;
    hp[idx] = h[(size_t)perm[a]*64 + f] * vals[a];
}

__global__ void k_zero(float* __restrict__ p, int nelem) {
    int i = blockIdx.x * blockDim.x + threadIdx.x;
    if (i < nelem) p[i] = 0.f;
}

__global__ void k_fillsel(int* __restrict__ sel, int n) {
    int i = blockIdx.x * blockDim.x + threadIdx.x;
    if (i < n) sel[i] = -1;
}

__global__ void k_setsel(int* __restrict__ sel, const int* __restrict__ perm, int k) {
    int i = blockIdx.x * blockDim.x + threadIdx.x;
    if (i < k) sel[perm[i]] = i;
}

// ---------------- pair-count augment: exact A1 in one pass -------------------
__global__ void k_pair(const int* __restrict__ off, const int* __restrict__ idx,
                       const int* __restrict__ sel, float* __restrict__ A1,
                       int n, int k1) {
    __shared__ int lists[8][128];
    int warp = threadIdx.x >> 5;
    int lane = threadIdx.x & 31;
    int j = blockIdx.x * 8 + warp;
    int* lst = lists[warp];
    int s = off[j];
    int e = off[j + 1];
    int total = e - s + 1; // + self-loop
    int cnt = 0;
    for (int t0 = 0; t0 < total; t0 += 32) {
        int m = t0 + lane;
        int a = -1;
        if (m < total) {
            int u = (m < total - 1) ? idx[s + m] : j;
            a = sel[u];
        }
        unsigned msk = __ballot_sync(0xffffffffu, a >= 0);
        if (a >= 0) lst[cnt + __popc(msk & ((1u << lane) - 1u))] = a;
        cnt += __popc(msk);
    }
    __syncwarp();
    for (int p = lane; p < cnt * cnt; p += 32) {
        int a = p / cnt;
        int b = p - a * cnt;
        if (a != b) atomicAdd(&A1[(size_t)lst[a] * k1 + lst[b]], 1.0f);
    }
}

// ---------------- Ra gathers --------------------------------------------------
__global__ void k_gather_ra(const float* __restrict__ A, const int* __restrict__ perm,
                            float* __restrict__ Ra, int k, int m) {
    int idx = blockIdx.x * blockDim.x + threadIdx.x;
    if (idx >= k * m) return;
    int a = idx / m;
    int j = idx - a * m;
    int pa = perm[a];
    float v = A[(size_t)pa * m + j];
    if (j == pa) v += 1.f;
    Ra[idx] = v;
}

__global__ void k_gather_ra16(const float* __restrict__ A, const int* __restrict__ perm,
                              __nv_bfloat16* __restrict__ Ra, int k, int m) {
    int idx = blockIdx.x * blockDim.x + threadIdx.x;
    if (idx >= k * m) return;
    int a = idx / m;
    int j = idx - a * m;
    int pa = perm[a];
    float v = A[(size_t)pa * m + j];
    if (j == pa) v += 1.f;
    Ra[idx] = __float2bfloat16(v); // exact: small integers
}

// ---------------- fp32 ramm (level 2) ----------------------------------------
__global__ void k_ramm(const float* __restrict__ Ra, float* __restrict__ C, int k, int m) {
    __shared__ float sA[64][33];
    __shared__ float sB[64][33];
    int tid = threadIdx.x; // 256
    int tx = tid & 15;
    int ty = tid >> 4;
    int rb = blockIdx.x * 64;
    int cb = blockIdx.y * 64;
    float acc[4][4];
    #pragma unroll
    for (int i = 0; i < 4; i++) {
        #pragma unroll
        for (int j = 0; j < 4; j++) acc[i][j] = 0.f;
    }
    for (int kb = 0; kb < m; kb += 32) {
        for (int q = tid; q < 512; q += 256) {
            int r = q >> 3;
            int c4 = (q & 7) * 4;
            float4 v = *(const float4*)(Ra + (size_t)(rb + r) * m + kb + c4);
            sA[r][c4] = v.x; sA[r][c4+1] = v.y; sA[r][c4+2] = v.z; sA[r][c4+3] = v.w;
            float4 u = *(const float4*)(Ra + (size_t)(cb + r) * m + kb + c4);
            sB[r][c4] = u.x; sB[r][c4+1] = u.y; sB[r][c4+2] = u.z; sB[r][c4+3] = u.w;
        }
        __syncthreads();
        #pragma unroll
        for (int w = 0; w < 32; w++) {
            float a0 = sA[ty*4+0][w];
            float a1 = sA[ty*4+1][w];
            float a2 = sA[ty*4+2][w];
            float a3 = sA[ty*4+3][w];
            float b0 = sB[tx*4+0][w];
            float b1 = sB[tx*4+1][w];
            float b2 = sB[tx*4+2][w];
            float b3 = sB[tx*4+3][w];
            acc[0][0] += a0*b0; acc[0][1] += a0*b1; acc[0][2] += a0*b2; acc[0][3] += a0*b3;
            acc[1][0] += a1*b0; acc[1][1] += a1*b1; acc[1][2] += a1*b2; acc[1][3] += a1*b3;
            acc[2][0] += a2*b0; acc[2][1] += a2*b1; acc[2][2] += a2*b2; acc[2][3] += a2*b3;
            acc[3][0] += a3*b0; acc[3][1] += a3*b1; acc[3][2] += a3*b2; acc[3][3] += a3*b3;
        }
        __syncthreads();
    }
    #pragma unroll
    for (int i = 0; i < 4; i++) {
        int gr = rb + ty*4 + i;
        #pragma unroll
        for (int j = 0; j < 4; j++) {
            int gc = cb + tx*4 + j;
            C[(size_t)gr * k + gc] = (gr == gc) ? 0.f : acc[i][j];
        }
    }
}

// ---------------- bf16 mma.sync ramm (level 1): C = Ra @ Ra^T, exact ---------
__global__ void __launch_bounds__(128) k_ramm_mma(const __nv_bfloat16* __restrict__ Ra,
                                                  float* __restrict__ C, int k, int m) {
    int w = threadIdx.x >> 5;  // warp 0..3, each does a 16-row band
    int l = threadIdx.x & 31;
    int rb = blockIdx.x * 64 + w * 16;
    int cb = blockIdx.y * 64;
    int lr = l >> 2;   // 0..7
    int lc = l & 3;    // 0..3
    float acc[8][4];
    #pragma unroll
    for (int t = 0; t < 8; t++) {
        #pragma unroll
        for (int j = 0; j < 4; j++) acc[t][j] = 0.f;
    }
    const __nv_bfloat16* Abase = Ra + (size_t)(rb + lr) * m + lc * 2;
    const __nv_bfloat16* Bbase = Ra + (size_t)(cb + lr) * m + lc * 2;
    for (int kb = 0; kb < m; kb += 16) {
        unsigned a0 = *(const unsigned*)(Abase + kb);
        unsigned a1 = *(const unsigned*)(Abase + (size_t)8 * m + kb);
        unsigned a2 = *(const unsigned*)(Abase + kb + 8);
        unsigned a3 = *(const unsigned*)(Abase + (size_t)8 * m + kb + 8);
        #pragma unroll
        for (int t = 0; t < 8; t++) {
            unsigned b0 = *(const unsigned*)(Bbase + (size_t)t * 8 * m + kb);
            unsigned b1 = *(const unsigned*)(Bbase + (size_t)t * 8 * m + kb + 8);
            asm volatile(
                "mma.sync.aligned.m16n8k16.row.col.f32.bf16.bf16.f32 "
                "{%0,%1,%2,%3}, {%4,%5,%6,%7}, {%8,%9}, {%0,%1,%2,%3};"
                : "+f"(acc[t][0]), "+f"(acc[t][1]), "+f"(acc[t][2]), "+f"(acc[t][3])
                : "r"(a0), "r"(a1), "r"(a2), "r"(a3), "r"(b0), "r"(b1));
        }
    }
    #pragma unroll
    for (int t = 0; t < 8; t++) {
        int row0 = rb + lr;
        int row1 = rb + lr + 8;
        int col = cb + t * 8 + lc * 2;
        float v0 = (row0 == col)     ? 0.f : acc[t][0];
        float v1 = (row0 == col + 1) ? 0.f : acc[t][1];
        float v2 = (row1 == col)     ? 0.f : acc[t][2];
        float v3 = (row1 == col + 1) ? 0.f : acc[t][3];
        *(float2*)&C[(size_t)row0 * k + col] = make_float2(v0, v1);
        *(float2*)&C[(size_t)row1 * k + col] = make_float2(v2, v3);
    }
}

// ---------------- scatter / final --------------------------------------------
__global__ void k_scatter_add(float* __restrict__ res, const int* __restrict__ perm,
                              const float* __restrict__ hsub, int k) {
    int idx = blockIdx.x * blockDim.x + threadIdx.x;
    if (idx >= k * 64) return;
    int a = idx >> 6;
    int f = idx & 63;
    res[(size_t)perm[a]*64 + f] += hsub[idx];
}

__global__ void k_final(const float* __restrict__ g, const float* __restrict__ fcw,
                        const float* __restrict__ fcb, const float* __restrict__ prob,
                        float* __restrict__ out, int n) {
    int gw = (blockIdx.x * blockDim.x + threadIdx.x) >> 5;
    int lane = threadIdx.x & 31;
    if (gw >= n) return;
    float v = fmaxf(g[(size_t)gw*64 + lane], 0.f)      * fcw[lane]
            + fmaxf(g[(size_t)gw*64 + 32 + lane], 0.f) * fcw[32 + lane];
    for (int o = 16; o; o >>= 1) v += __shfl_xor_sync(0xffffffffu, v, o);
    if (lane == 0) out[gw] = v / (1.f - prob[0]) + fcb[0];
}

// =============================================================================
extern "C" void kernel_launch(void* const* d_in, const int* in_sizes, int n_in,
                              void* d_out, int out_size) {
    (void)in_sizes;
    (void)n_in;
    (void)out_size;
    const float* x    = (const float*)d_in[0];
    const float* adj  = (const float*)d_in[1];
    const float* prob = (const float*)d_in[2];
    const float* dW   = (const float*)d_in[3];
    const float* db   = (const float*)d_in[4];
    const float* pw   = (const float*)d_in[5];
    const float* uW   = (const float*)d_in[6];
    const float* ub   = (const float*)d_in[7];
    const float* fcw  = (const float*)d_in[8];
    const float* fcb  = (const float*)d_in[9];
    float* out = (float*)d_out;

    void *pv;
    cudaGetSymbolAddress(&pv, g_A1);    float* A1 = (float*)pv;
    cudaGetSymbolAddress(&pv, g_A2);    float* A2 = (float*)pv;
    cudaGetSymbolAddress(&pv, g_A3);    float* A3 = (float*)pv;
    cudaGetSymbolAddress(&pv, g_Ra);    float* Ra = (float*)pv;
    cudaGetSymbolAddress(&pv, g_Ra16);  __nv_bfloat16* Ra16 = (__nv_bfloat16*)pv;
    cudaGetSymbolAddress(&pv, g_h0);    float* h0 = (float*)pv;
    cudaGetSymbolAddress(&pv, g_h1);    float* h1 = (float*)pv;
    cudaGetSymbolAddress(&pv, g_h2);    float* h2 = (float*)pv;
    cudaGetSymbolAddress(&pv, g_h3);    float* h3 = (float*)pv;
    cudaGetSymbolAddress(&pv, g_hp);    float* hp = (float*)pv;
    cudaGetSymbolAddress(&pv, g_ys);    float* ys = (float*)pv;
    cudaGetSymbolAddress(&pv, g_u);     float* u  = (float*)pv;
    cudaGetSymbolAddress(&pv, g_dinv0); float* dinv0 = (float*)pv;
    cudaGetSymbolAddress(&pv, g_dinv1); float* dinv1 = (float*)pv;
    cudaGetSymbolAddress(&pv, g_dinv2); float* dinv2 = (float*)pv;
    cudaGetSymbolAddress(&pv, g_dinv3); float* dinv3 = (float*)pv;
    cudaGetSymbolAddress(&pv, g_perm0); int* perm0 = (int*)pv;
    cudaGetSymbolAddress(&pv, g_perm1); int* perm1 = (int*)pv;
    cudaGetSymbolAddress(&pv, g_perm2); int* perm2 = (int*)pv;
    cudaGetSymbolAddress(&pv, g_vals);  float* vals = (float*)pv;
    cudaGetSymbolAddress(&pv, g_score); float* score = (float*)pv;
    cudaGetSymbolAddress(&pv, g_deg);   int* deg  = (int*)pv;
    cudaGetSymbolAddress(&pv, g_offA);  int* offA = (int*)pv;
    cudaGetSymbolAddress(&pv, g_idxA);  int* idxA = (int*)pv;
    cudaGetSymbolAddress(&pv, g_valA);  float* valA = (float*)pv;
    cudaGetSymbolAddress(&pv, g_off1);  int* off1 = (int*)pv;
    cudaGetSymbolAddress(&pv, g_idx1);  int* idx1 = (int*)pv;
    cudaGetSymbolAddress(&pv, g_val1);  float* val1 = (float*)pv;
    cudaGetSymbolAddress(&pv, g_sel);   int* sel  = (int*)pv;

    // ---------------- CSR(adj) + dinv0 -----------------------
    k_deg<<<512, 256>>>(adj, 4096, deg, dinv0);
    k_scan<<<1, 1024>>>(deg, offA, 4096);
    k_fill<<<512, 256>>>(adj, offA, idxA, valA, 4096);

    // ---------------- down level 0 (n = 4096) ----------------
    k_featw<<<64, 256>>>(x, dW, dinv0, ys, 4096);
    k_prop_sp<<<512, 256>>>(offA, idxA, valA, ys, dinv0, db, h0, 4096, 1);

    // ---------------- pool 0: 4096 -> 2048 -------------------
    k_invpnorm<<<1, 32>>>(pw);
    k_score<<<512, 256>>>(h0, pw, score, 4096);
    k_topk<<<1, 1024>>>(score, 4096, 2048, perm0, vals);
    k_gather_h<<<512, 256>>>(h0, perm0, vals, hp, 2048);
    k_fillsel<<<16, 256>>>(sel, 4096);
    k_setsel<<<8, 256>>>(sel, perm0, 2048);
    k_zero<<<16384, 256>>>(A1, 2048*2048);
    k_pair<<<512, 256>>>(offA, idxA, sel, A1, 4096, 2048);
    k_dinv<<<2048, 256>>>(A1, 2048, dinv1);
    k_deg<<<256, 256>>>(A1, 2048, deg, (float*)0);
    k_scan<<<1, 1024>>>(deg, off1, 2048);
    k_fill<<<256, 256>>>(A1, off1, idx1, val1, 2048);
    k_featw<<<32, 256>>>(hp, dW + 1*4096, dinv1, ys, 2048);
    k_prop_sp<<<256, 256>>>(off1, idx1, val1, ys, dinv1, db + 64, h1, 2048, 1);

    // ---------------- pool 1: 2048 -> 1024 -------------------
    k_invpnorm<<<1, 32>>>(pw + 64);
    k_score<<<256, 256>>>(h1, pw + 64, score, 2048);
    k_topk<<<1, 1024>>>(score, 2048, 1024, perm1, vals);
    k_gather_h<<<256, 256>>>(h1, perm1, vals, hp, 1024);
    k_gather_ra16<<<8192, 256>>>(A1, perm1, Ra16, 1024, 2048);
    k_ramm_mma<<<dim3(16, 16), 128>>>(Ra16, A2, 1024, 2048);
    k_dinv<<<1024, 256>>>(A2, 1024, dinv2);
    k_featw<<<16, 256>>>(hp, dW + 2*4096, dinv2, ys, 1024);
    k_prop<<<32, 256>>>(A2, ys, dinv2, db + 128, h2, 1024, 1);

    // ---------------- pool 2: 1024 -> 512 --------------------
    k_invpnorm<<<1, 32>>>(pw + 128);
    k_score<<<128, 256>>>(h2, pw + 128, score, 1024);
    k_topk<<<1, 1024>>>(score, 1024, 512, perm2, vals);
    k_gather_h<<<128, 256>>>(h2, perm2, vals, hp, 512);
    k_gather_ra<<<2048, 256>>>(A2, perm2, Ra, 512, 1024);
    k_ramm<<<dim3(8, 8), 256>>>(Ra, A3, 512, 1024);
    k_dinv<<<512, 256>>>(A3, 512, dinv3);
    k_featw<<<8, 256>>>(hp, dW + 3*4096, dinv3, ys, 512);
    k_prop<<<16, 256>>>(A3, ys, dinv3, db + 192, h3, 512, 1);

    // ---------------- up 0: scatter into h2 (1024), relu -----
    k_scatter_add<<<128, 256>>>(h2, perm2, h3, 512);
    k_featw<<<16, 256>>>(h2, uW, dinv2, ys, 1024);
    k_prop<<<32, 256>>>(A2, ys, dinv2, ub, u, 1024, 1);

    // ---------------- up 1: scatter into h1 (2048), relu -----
    k_scatter_add<<<256, 256>>>(h1, perm1, u, 1024);
    k_featw<<<32, 256>>>(h1, uW + 4096, dinv1, ys, 2048);
    k_prop_sp<<<256, 256>>>(off1, idx1, val1, ys, dinv1, ub + 64, u, 2048, 1);

    // ---------------- up 2: scatter into h0 (4096), no relu --
    k_scatter_add<<<512, 256>>>(h0, perm0, u, 2048);
    k_featw<<<64, 256>>>(h0, uW + 8192, dinv0, ys, 4096);
    k_prop_sp<<<512, 256>>>(offA, idxA, valA, ys, dinv0, ub + 128, u, 4096, 0);

    // ---------------- final: relu, dropout(0), fc ------------
    k_final<<<512, 256>>>(u, fcw, fcb, prob, out, 4096);
}

// round 6
// speedup vs baseline: 1.9826x; 1.0335x over previous
#include <cuda_runtime.h>
#include <cuda_bf16.h>
#include <math.h>

// ---------------- static device scratch (no allocations allowed) -------------
__device__ float         g_A1[2048u*2048u];
__device__ float         g_A2[1024u*1024u];
__device__ float         g_A3[512u*512u];
__device__ float         g_Ra[512u*1024u];
__device__ __nv_bfloat16 g_Ra16[1024u*2048u];
__device__ float g_h0[4096*64];
__device__ float g_h1[2048*64];
__device__ float g_h2[1024*64];
__device__ float g_ys[4096*64];
__device__ float g_u[4096*64];
__device__ float g_dinv0[4096];
__device__ float g_dinv1[2048];
__device__ float g_dinv2[1024];
__device__ float g_dinv3[512];
__device__ int   g_perm0[2048];
__device__ int   g_perm1[1024];
__device__ int   g_perm2[512];
__device__ float g_vals[2048];
__device__ float g_score[4096];
__device__ int   g_deg[4096];
__device__ int   g_offA[4097];
__device__ int   g_idxA[4096u*1024u];
__device__ float g_valA[4096u*1024u];
__device__ int   g_off1[2049];
__device__ int   g_idx1[2048u*2048u];
__device__ float g_val1[2048u*2048u];
__device__ int   g_sel[4096];

// ========================= CSR construction ==================================
__global__ void k_deg(const float* __restrict__ A, int n, int* __restrict__ deg,
                      float* __restrict__ dinvOrNull) {
    int row = blockIdx.x * 8 + (threadIdx.x >> 5);
    int lane = threadIdx.x & 31;
    const float* a = A + (size_t)row * n;
    int c = 0;
    for (int j = lane; j < n; j += 32) c += (a[j] != 0.f) ? 1 : 0;
    for (int o = 16; o; o >>= 1) c += __shfl_xor_sync(0xffffffffu, c, o);
    if (lane == 0) {
        deg[row] = c;
        if (dinvOrNull != 0) dinvOrNull[row] = 1.0f / sqrtf((float)c + 2.0f);
    }
}

__global__ void k_scan(const int* __restrict__ deg, int* __restrict__ off, int n) {
    __shared__ int s[4096];
    int t = threadIdx.x; // 1024 threads
    for (int i = t; i < n; i += 1024) s[i] = deg[i];
    __syncthreads();
    for (int d = 1; d < n; d <<= 1) {
        int v[4];
        int q = 0;
        for (int i = t; i < n; i += 1024) { v[q] = (i >= d) ? s[i - d] : 0; q++; }
        __syncthreads();
        q = 0;
        for (int i = t; i < n; i += 1024) { s[i] += v[q]; q++; }
        __syncthreads();
    }
    if (t == 0) off[0] = 0;
    for (int i = t; i < n; i += 1024) off[i + 1] = s[i];
}

// fill CSR; optionally compute dinv from weighted rowsum (exact: integer sums)
__global__ void k_fill(const float* __restrict__ A, const int* __restrict__ off,
                       int* __restrict__ idx, float* __restrict__ val, int n,
                       float* __restrict__ dinvOut) {
    int row = blockIdx.x * 8 + (threadIdx.x >> 5);
    int lane = threadIdx.x & 31;
    const float* a = A + (size_t)row * n;
    int ptr = off[row];
    float fsum = 0.f;
    for (int j0 = 0; j0 < n; j0 += 32) {
        float v = a[j0 + lane];
        fsum += v;
        unsigned msk = __ballot_sync(0xffffffffu, v != 0.f);
        if (v != 0.f) {
            int p = ptr + __popc(msk & ((1u << lane) - 1u));
            idx[p] = j0 + lane;
            val[p] = v;
        }
        ptr += __popc(msk);
    }
    if (dinvOut != 0) {
        for (int o = 16; o; o >>= 1) fsum += __shfl_xor_sync(0xffffffffu, fsum, o);
        if (lane == 0) dinvOut[row] = 1.0f / sqrtf(fsum + 2.0f);
    }
}

// ---------------- dinv[i] = 1/sqrt(rowsum(A)+2) (dense, weighted) ------------
__global__ void k_dinv(const float* __restrict__ A, int n, float* __restrict__ dinv) {
    int row = blockIdx.x;
    const float* a = A + (size_t)row * n;
    float s = 0.f;
    for (int j = threadIdx.x; j < n; j += blockDim.x) s += a[j];
    for (int o = 16; o; o >>= 1) s += __shfl_xor_sync(0xffffffffu, s, o);
    __shared__ float red[8];
    int lane = threadIdx.x & 31;
    int warp = threadIdx.x >> 5;
    if (lane == 0) red[warp] = s;
    __syncthreads();
    if (threadIdx.x == 0) {
        float t = 0.f;
        #pragma unroll
        for (int w = 0; w < 8; w++) t += red[w];
        dinv[row] = 1.0f / sqrtf(t + 2.0f);
    }
}

// ---------------- ys = dinv .* ((gather(X)) @ W), 4x4 register blocked -------
__global__ void k_featw(const float* __restrict__ X, const float* __restrict__ W,
                        const float* __restrict__ dinv, const int* __restrict__ perm,
                        const float* __restrict__ vals, float* __restrict__ ys, int n) {
    __shared__ float Ws[64][64];   // [k][c]
    __shared__ float Xs[64][65];   // [r][k]
    int tid = threadIdx.x; // 256
    int rowb = blockIdx.x * 64;
    const float4* W4 = (const float4*)W;
    float4* Ws4 = (float4*)&Ws[0][0];
    for (int i = tid; i < 1024; i += 256) Ws4[i] = W4[i];
    for (int i = tid; i < 1024; i += 256) {
        int r = i >> 4;
        int c4 = (i & 15) << 2;
        int rs = rowb + r;
        const float* src;
        float scale = 1.f;
        if (perm != 0) { src = X + (size_t)perm[rs] * 64; scale = vals[rs]; }
        else           { src = X + (size_t)rs * 64; }
        float4 v = *(const float4*)(src + c4);
        Xs[r][c4+0] = v.x * scale;
        Xs[r][c4+1] = v.y * scale;
        Xs[r][c4+2] = v.z * scale;
        Xs[r][c4+3] = v.w * scale;
    }
    __syncthreads();
    int tx = tid & 15;
    int ty = tid >> 4;
    float4 acc[4];
    #pragma unroll
    for (int i = 0; i < 4; i++) acc[i] = make_float4(0.f, 0.f, 0.f, 0.f);
    #pragma unroll 4
    for (int k = 0; k < 64; k++) {
        float4 b = *(float4*)&Ws[k][tx * 4];
        float a0 = Xs[ty*4+0][k];
        float a1 = Xs[ty*4+1][k];
        float a2 = Xs[ty*4+2][k];
        float a3 = Xs[ty*4+3][k];
        acc[0].x += a0*b.x; acc[0].y += a0*b.y; acc[0].z += a0*b.z; acc[0].w += a0*b.w;
        acc[1].x += a1*b.x; acc[1].y += a1*b.y; acc[1].z += a1*b.z; acc[1].w += a1*b.w;
        acc[2].x += a2*b.x; acc[2].y += a2*b.y; acc[2].z += a2*b.z; acc[2].w += a2*b.w;
        acc[3].x += a3*b.x; acc[3].y += a3*b.y; acc[3].z += a3*b.z; acc[3].w += a3*b.w;
    }
    #pragma unroll
    for (int i = 0; i < 4; i++) {
        int r = rowb + ty*4 + i;
        float d = dinv[r];
        float4 o = make_float4(acc[i].x*d, acc[i].y*d, acc[i].z*d, acc[i].w*d);
        *(float4*)(ys + (size_t)r * 64 + tx * 4) = o;
    }
}

// ---- sparse prop: v = act(d*(A@ys) + 2d*ys + b); write h[row] or h[perm[row]] += v
__global__ void k_prop_sp(const int* __restrict__ off, const int* __restrict__ idx,
                          const float* __restrict__ val, const float* __restrict__ ys,
                          const float* __restrict__ dinv, const float* __restrict__ bias,
                          float* __restrict__ h, int n, int relu,
                          const int* __restrict__ permOut) {
    int row = blockIdx.x * 8 + (threadIdx.x >> 5);
    int lane = threadIdx.x & 31;
    if (row >= n) return;
    int s = off[row];
    int e = off[row + 1];
    float a0 = 0.f;
    float a1 = 0.f;
    for (int m = s; m < e; m++) {
        int j = idx[m];
        float w = val[m];
        a0 += w * ys[(size_t)j * 64 + lane];
        a1 += w * ys[(size_t)j * 64 + 32 + lane];
    }
    float d = dinv[row];
    float v0 = d * a0 + 2.f * d * ys[(size_t)row * 64 + lane] + bias[lane];
    float v1 = d * a1 + 2.f * d * ys[(size_t)row * 64 + 32 + lane] + bias[32 + lane];
    if (relu) { v0 = fmaxf(v0, 0.f); v1 = fmaxf(v1, 0.f); }
    if (permOut != 0) {
        float* dst = h + (size_t)permOut[row] * 64;
        dst[lane] += v0;
        dst[32 + lane] += v1;
    } else {
        h[(size_t)row * 64 + lane] = v0;
        h[(size_t)row * 64 + 32 + lane] = v1;
    }
}

// ---------------- dense prop -------------------------------------------------
__global__ void k_prop(const float* __restrict__ A, const float* __restrict__ ys,
                       const float* __restrict__ dinv, const float* __restrict__ bias,
                       float* __restrict__ hout, int n, int relu,
                       const int* __restrict__ permOut) {
    __shared__ float sA[32][33];
    __shared__ float sB[32][64];
    int tid = threadIdx.x; // 256
    int tx = tid & 15;
    int ty = tid >> 4;
    int rowb = blockIdx.x * 32;
    float acc[2][4] = {{0.f,0.f,0.f,0.f},{0.f,0.f,0.f,0.f}};
    for (int kb = 0; kb < n; kb += 32) {
        int r0 = tid >> 3;
        int c0 = (tid & 7) * 4;
        float4 v = *(const float4*)(A + (size_t)(rowb + r0) * n + kb + c0);
        sA[r0][c0] = v.x; sA[r0][c0+1] = v.y; sA[r0][c0+2] = v.z; sA[r0][c0+3] = v.w;
        for (int q = tid; q < 512; q += 256) {
            int r = q >> 4;
            int c4 = (q & 15) * 4;
            *(float4*)&sB[r][c4] = *(const float4*)(ys + (size_t)(kb + r) * 64 + c4);
        }
        __syncthreads();
        #pragma unroll
        for (int kk = 0; kk < 32; kk++) {
            float a0 = sA[ty*2+0][kk];
            float a1 = sA[ty*2+1][kk];
            float4 b = *(float4*)&sB[kk][tx*4];
            acc[0][0] += a0*b.x; acc[0][1] += a0*b.y; acc[0][2] += a0*b.z; acc[0][3] += a0*b.w;
            acc[1][0] += a1*b.x; acc[1][1] += a1*b.y; acc[1][2] += a1*b.z; acc[1][3] += a1*b.w;
        }
        __syncthreads();
    }
    #pragma unroll
    for (int i = 0; i < 2; i++) {
        int r = rowb + ty*2 + i;
        float d = dinv[r];
        int orow = (permOut != 0) ? permOut[r] : r;
        #pragma unroll
        for (int j = 0; j < 4; j++) {
            int c = tx*4 + j;
            float v = d*acc[i][j] + 2.f*d*ys[(size_t)r*64 + c] + bias[c];
            if (relu) v = fmaxf(v, 0.f);
            if (permOut != 0) hout[(size_t)orow*64 + c] += v;
            else              hout[(size_t)orow*64 + c] = v;
        }
    }
}

// ---------------- score (pnorm folded in, deterministic) ---------------------
__global__ void k_score(const float* __restrict__ h, const float* __restrict__ p,
                        float* __restrict__ score, int n) {
    int gw = (blockIdx.x * blockDim.x + threadIdx.x) >> 5;
    int lane = threadIdx.x & 31;
    if (gw >= n) return;
    float pl = p[lane];
    float ph = p[32 + lane];
    float pn = pl*pl + ph*ph;
    float d = h[(size_t)gw*64 + lane] * pl + h[(size_t)gw*64 + 32 + lane] * ph;
    for (int o = 16; o; o >>= 1) {
        d  += __shfl_xor_sync(0xffffffffu, d, o);
        pn += __shfl_xor_sync(0xffffffffu, pn, o);
    }
    if (lane == 0) score[gw] = tanhf(d * (1.0f / sqrtf(pn)));
}

__global__ void k_topk(const float* __restrict__ score, int n, int k,
                       int* __restrict__ perm, float* __restrict__ vals) {
    __shared__ float ss[4096];
    __shared__ int   si[4096];
    int t = threadIdx.x; // 1024
    for (int i = t; i < n; i += blockDim.x) { ss[i] = score[i]; si[i] = i; }
    __syncthreads();
    for (int kk = 2; kk <= n; kk <<= 1) {
        for (int j = kk >> 1; j > 0; j >>= 1) {
            for (int i = t; i < n; i += blockDim.x) {
                int ixj = i ^ j;
                if (ixj > i) {
                    float s1 = ss[i];
                    float s2 = ss[ixj];
                    int i1 = si[i];
                    int i2 = si[ixj];
                    bool b21 = (s2 > s1) || (s2 == s1 && i2 < i1);
                    bool dir = ((i & kk) == 0);
                    bool sw = dir ? b21 : (!b21);
                    if (sw) { ss[i] = s2; ss[ixj] = s1; si[i] = i2; si[ixj] = i1; }
                }
            }
            __syncthreads();
        }
    }
    for (int i = t; i < k; i += blockDim.x) { perm[i] = si[i]; vals[i] = ss[i]; }
}

// ---------------- zero A1 + sel=-1 + deg=0 in one launch ---------------------
__global__ void k_zero_sel(float* __restrict__ A, int nelem, int* __restrict__ sel,
                           int n, int* __restrict__ deg, int nd) {
    int i = blockIdx.x * blockDim.x + threadIdx.x;
    if (i < nelem) A[i] = 0.f;
    if (i < n) sel[i] = -1;
    if (i < nd) deg[i] = 0;
}

__global__ void k_setsel(int* __restrict__ sel, const int* __restrict__ perm, int k) {
    int i = blockIdx.x * blockDim.x + threadIdx.x;
    if (i < k) sel[perm[i]] = i;
}

// ---------------- pair-count augment: exact A1 + nnz counting ----------------
__global__ void k_pair(const int* __restrict__ off, const int* __restrict__ idx,
                       const int* __restrict__ sel, float* __restrict__ A1,
                       int* __restrict__ deg, int n, int k1) {
    __shared__ int lists[8][128];
    int warp = threadIdx.x >> 5;
    int lane = threadIdx.x & 31;
    int j = blockIdx.x * 8 + warp;
    int* lst = lists[warp];
    int s = off[j];
    int e = off[j + 1];
    int total = e - s + 1; // + self-loop
    int cnt = 0;
    for (int t0 = 0; t0 < total; t0 += 32) {
        int m = t0 + lane;
        int a = -1;
        if (m < total) {
            int u = (m < total - 1) ? idx[s + m] : j;
            a = sel[u];
        }
        unsigned msk = __ballot_sync(0xffffffffu, a >= 0);
        if (a >= 0) lst[cnt + __popc(msk & ((1u << lane) - 1u))] = a;
        cnt += __popc(msk);
    }
    __syncwarp();
    for (int p = lane; p < cnt * cnt; p += 32) {
        int a = p / cnt;
        int b = p - a * cnt;
        if (a != b) {
            float old = atomicAdd(&A1[(size_t)lst[a] * k1 + lst[b]], 1.0f);
            if (old == 0.f) atomicAdd(&deg[lst[a]], 1);
        }
    }
}

// ---------------- Ra gathers --------------------------------------------------
__global__ void k_gather_ra(const float* __restrict__ A, const int* __restrict__ perm,
                            float* __restrict__ Ra, int k, int m) {
    int idx = blockIdx.x * blockDim.x + threadIdx.x;
    if (idx >= k * m) return;
    int a = idx / m;
    int j = idx - a * m;
    int pa = perm[a];
    float v = A[(size_t)pa * m + j];
    if (j == pa) v += 1.f;
    Ra[idx] = v;
}

__global__ void k_gather_ra16(const float* __restrict__ A, const int* __restrict__ perm,
                              __nv_bfloat16* __restrict__ Ra, int k, int m) {
    int idx = blockIdx.x * blockDim.x + threadIdx.x;
    if (idx >= k * m) return;
    int a = idx / m;
    int j = idx - a * m;
    int pa = perm[a];
    float v = A[(size_t)pa * m + j];
    if (j == pa) v += 1.f;
    Ra[idx] = __float2bfloat16(v); // exact: small integers
}

// ---------------- fp32 ramm (level 2) ----------------------------------------
__global__ void k_ramm(const float* __restrict__ Ra, float* __restrict__ C, int k, int m) {
    __shared__ float sA[64][33];
    __shared__ float sB[64][33];
    int tid = threadIdx.x; // 256
    int tx = tid & 15;
    int ty = tid >> 4;
    int rb = blockIdx.x * 64;
    int cb = blockIdx.y * 64;
    float acc[4][4];
    #pragma unroll
    for (int i = 0; i < 4; i++) {
        #pragma unroll
        for (int j = 0; j < 4; j++) acc[i][j] = 0.f;
    }
    for (int kb = 0; kb < m; kb += 32) {
        for (int q = tid; q < 512; q += 256) {
            int r = q >> 3;
            int c4 = (q & 7) * 4;
            float4 v = *(const float4*)(Ra + (size_t)(rb + r) * m + kb + c4);
            sA[r][c4] = v.x; sA[r][c4+1] = v.y; sA[r][c4+2] = v.z; sA[r][c4+3] = v.w;
            float4 u = *(const float4*)(Ra + (size_t)(cb + r) * m + kb + c4);
            sB[r][c4] = u.x; sB[r][c4+1] = u.y; sB[r][c4+2] = u.z; sB[r][c4+3] = u.w;
        }
        __syncthreads();
        #pragma unroll
        for (int w = 0; w < 32; w++) {
            float a0 = sA[ty*4+0][w];
            float a1 = sA[ty*4+1][w];
            float a2 = sA[ty*4+2][w];
            float a3 = sA[ty*4+3][w];
            float b0 = sB[tx*4+0][w];
            float b1 = sB[tx*4+1][w];
            float b2 = sB[tx*4+2][w];
            float b3 = sB[tx*4+3][w];
            acc[0][0] += a0*b0; acc[0][1] += a0*b1; acc[0][2] += a0*b2; acc[0][3] += a0*b3;
            acc[1][0] += a1*b0; acc[1][1] += a1*b1; acc[1][2] += a1*b2; acc[1][3] += a1*b3;
            acc[2][0] += a2*b0; acc[2][1] += a2*b1; acc[2][2] += a2*b2; acc[2][3] += a2*b3;
            acc[3][0] += a3*b0; acc[3][1] += a3*b1; acc[3][2] += a3*b2; acc[3][3] += a3*b3;
        }
        __syncthreads();
    }
    #pragma unroll
    for (int i = 0; i < 4; i++) {
        int gr = rb + ty*4 + i;
        #pragma unroll
        for (int j = 0; j < 4; j++) {
            int gc = cb + tx*4 + j;
            C[(size_t)gr * k + gc] = (gr == gc) ? 0.f : acc[i][j];
        }
    }
}

// ---------------- bf16 mma.sync ramm (level 1): C = Ra @ Ra^T, exact ---------
__global__ void __launch_bounds__(128) k_ramm_mma(const __nv_bfloat16* __restrict__ Ra,
                                                  float* __restrict__ C, int k, int m) {
    int w = threadIdx.x >> 5;  // warp 0..3, each does a 16-row band
    int l = threadIdx.x & 31;
    int rb = blockIdx.x * 64 + w * 16;
    int cb = blockIdx.y * 64;
    int lr = l >> 2;   // 0..7
    int lc = l & 3;    // 0..3
    float acc[8][4];
    #pragma unroll
    for (int t = 0; t < 8; t++) {
        #pragma unroll
        for (int j = 0; j < 4; j++) acc[t][j] = 0.f;
    }
    const __nv_bfloat16* Abase = Ra + (size_t)(rb + lr) * m + lc * 2;
    const __nv_bfloat16* Bbase = Ra + (size_t)(cb + lr) * m + lc * 2;
    for (int kb = 0; kb < m; kb += 16) {
        unsigned a0 = *(const unsigned*)(Abase + kb);
        unsigned a1 = *(const unsigned*)(Abase + (size_t)8 * m + kb);
        unsigned a2 = *(const unsigned*)(Abase + kb + 8);
        unsigned a3 = *(const unsigned*)(Abase + (size_t)8 * m + kb + 8);
        #pragma unroll
        for (int t = 0; t < 8; t++) {
            unsigned b0 = *(const unsigned*)(Bbase + (size_t)t * 8 * m + kb);
            unsigned b1 = *(const unsigned*)(Bbase + (size_t)t * 8 * m + kb + 8);
            asm volatile(
                "mma.sync.aligned.m16n8k16.row.col.f32.bf16.bf16.f32 "
                "{%0,%1,%2,%3}, {%4,%5,%6,%7}, {%8,%9}, {%0,%1,%2,%3};"
                : "+f"(acc[t][0]), "+f"(acc[t][1]), "+f"(acc[t][2]), "+f"(acc[t][3])
                : "r"(a0), "r"(a1), "r"(a2), "r"(a3), "r"(b0), "r"(b1));
        }
    }
    #pragma unroll
    for (int t = 0; t < 8; t++) {
        int row0 = rb + lr;
        int row1 = rb + lr + 8;
        int col = cb + t * 8 + lc * 2;
        float v0 = (row0 == col)     ? 0.f : acc[t][0];
        float v1 = (row0 == col + 1) ? 0.f : acc[t][1];
        float v2 = (row1 == col)     ? 0.f : acc[t][2];
        float v3 = (row1 == col + 1) ? 0.f : acc[t][3];
        *(float2*)&C[(size_t)row0 * k + col] = make_float2(v0, v1);
        *(float2*)&C[(size_t)row1 * k + col] = make_float2(v2, v3);
    }
}

// ---------------- final: relu, dropout(0), fc --------------------------------
__global__ void k_final(const float* __restrict__ g, const float* __restrict__ fcw,
                        const float* __restrict__ fcb, const float* __restrict__ prob,
                        float* __restrict__ out, int n) {
    int gw = (blockIdx.x * blockDim.x + threadIdx.x) >> 5;
    int lane = threadIdx.x & 31;
    if (gw >= n) return;
    float v = fmaxf(g[(size_t)gw*64 + lane], 0.f)      * fcw[lane]
            + fmaxf(g[(size_t)gw*64 + 32 + lane], 0.f) * fcw[32 + lane];
    for (int o = 16; o; o >>= 1) v += __shfl_xor_sync(0xffffffffu, v, o);
    if (lane == 0) out[gw] = v / (1.f - prob[0]) + fcb[0];
}

// =============================================================================
extern "C" void kernel_launch(void* const* d_in, const int* in_sizes, int n_in,
                              void* d_out, int out_size) {
    (void)in_sizes;
    (void)n_in;
    (void)out_size;
    const float* x    = (const float*)d_in[0];
    const float* adj  = (const float*)d_in[1];
    const float* prob = (const float*)d_in[2];
    const float* dW   = (const float*)d_in[3];
    const float* db   = (const float*)d_in[4];
    const float* pw   = (const float*)d_in[5];
    const float* uW   = (const float*)d_in[6];
    const float* ub   = (const float*)d_in[7];
    const float* fcw  = (const float*)d_in[8];
    const float* fcb  = (const float*)d_in[9];
    float* out = (float*)d_out;

    void* pv;
    cudaGetSymbolAddress(&pv, g_A1);    float* A1 = (float*)pv;
    cudaGetSymbolAddress(&pv, g_A2);    float* A2 = (float*)pv;
    cudaGetSymbolAddress(&pv, g_A3);    float* A3 = (float*)pv;
    cudaGetSymbolAddress(&pv, g_Ra);    float* Ra = (float*)pv;
    cudaGetSymbolAddress(&pv, g_Ra16);  __nv_bfloat16* Ra16 = (__nv_bfloat16*)pv;
    cudaGetSymbolAddress(&pv, g_h0);    float* h0 = (float*)pv;
    cudaGetSymbolAddress(&pv, g_h1);    float* h1 = (float*)pv;
    cudaGetSymbolAddress(&pv, g_h2);    float* h2 = (float*)pv;
    cudaGetSymbolAddress(&pv, g_ys);    float* ys = (float*)pv;
    cudaGetSymbolAddress(&pv, g_u);     float* u  = (float*)pv;
    cudaGetSymbolAddress(&pv, g_dinv0); float* dinv0 = (float*)pv;
    cudaGetSymbolAddress(&pv, g_dinv1); float* dinv1 = (float*)pv;
    cudaGetSymbolAddress(&pv, g_dinv2); float* dinv2 = (float*)pv;
    cudaGetSymbolAddress(&pv, g_dinv3); float* dinv3 = (float*)pv;
    cudaGetSymbolAddress(&pv, g_perm0); int* perm0 = (int*)pv;
    cudaGetSymbolAddress(&pv, g_perm1); int* perm1 = (int*)pv;
    cudaGetSymbolAddress(&pv, g_perm2); int* perm2 = (int*)pv;
    cudaGetSymbolAddress(&pv, g_vals);  float* vals = (float*)pv;
    cudaGetSymbolAddress(&pv, g_score); float* score = (float*)pv;
    cudaGetSymbolAddress(&pv, g_deg);   int* deg  = (int*)pv;
    cudaGetSymbolAddress(&pv, g_offA);  int* offA = (int*)pv;
    cudaGetSymbolAddress(&pv, g_idxA);  int* idxA = (int*)pv;
    cudaGetSymbolAddress(&pv, g_valA);  float* valA = (float*)pv;
    cudaGetSymbolAddress(&pv, g_off1);  int* off1 = (int*)pv;
    cudaGetSymbolAddress(&pv, g_idx1);  int* idx1 = (int*)pv;
    cudaGetSymbolAddress(&pv, g_val1);  float* val1 = (float*)pv;
    cudaGetSymbolAddress(&pv, g_sel);   int* sel  = (int*)pv;

    const int* nullperm = (const int*)0;
    const float* nullvals = (const float*)0;

    // ---------------- CSR(adj) + dinv0 -----------------------
    k_deg<<<512, 256>>>(adj, 4096, deg, dinv0);
    k_scan<<<1, 1024>>>(deg, offA, 4096);
    k_fill<<<512, 256>>>(adj, offA, idxA, valA, 4096, (float*)0);

    // ---------------- down level 0 (n = 4096) ----------------
    k_featw<<<64, 256>>>(x, dW, dinv0, nullperm, nullvals, ys, 4096);
    k_prop_sp<<<512, 256>>>(offA, idxA, valA, ys, dinv0, db, h0, 4096, 1, nullperm);

    // ---------------- pool 0: 4096 -> 2048 -------------------
    k_score<<<512, 256>>>(h0, pw, score, 4096);
    k_topk<<<1, 1024>>>(score, 4096, 2048, perm0, vals);
    k_zero_sel<<<16384, 256>>>(A1, 2048*2048, sel, 4096, deg, 2048);
    k_setsel<<<8, 256>>>(sel, perm0, 2048);
    k_pair<<<512, 256>>>(offA, idxA, sel, A1, deg, 4096, 2048);
    k_scan<<<1, 1024>>>(deg, off1, 2048);
    k_fill<<<256, 256>>>(A1, off1, idx1, val1, 2048, dinv1);

    // ---------------- down level 1 ---------------------------
    k_featw<<<32, 256>>>(h0, dW + 1*4096, dinv1, perm0, vals, ys, 2048);
    k_prop_sp<<<256, 256>>>(off1, idx1, val1, ys, dinv1, db + 64, h1, 2048, 1, nullperm);

    // ---------------- pool 1: 2048 -> 1024 -------------------
    k_score<<<256, 256>>>(h1, pw + 64, score, 2048);
    k_topk<<<1, 1024>>>(score, 2048, 1024, perm1, vals);
    k_gather_ra16<<<8192, 256>>>(A1, perm1, Ra16, 1024, 2048);
    k_ramm_mma<<<dim3(16, 16), 128>>>(Ra16, A2, 1024, 2048);
    k_dinv<<<1024, 256>>>(A2, 1024, dinv2);

    // ---------------- down level 2 ---------------------------
    k_featw<<<16, 256>>>(h1, dW + 2*4096, dinv2, perm1, vals, ys, 1024);
    k_prop<<<32, 256>>>(A2, ys, dinv2, db + 128, h2, 1024, 1, nullperm);

    // ---------------- pool 2: 1024 -> 512 --------------------
    k_score<<<128, 256>>>(h2, pw + 128, score, 1024);
    k_topk<<<1, 1024>>>(score, 1024, 512, perm2, vals);
    k_gather_ra<<<2048, 256>>>(A2, perm2, Ra, 512, 1024);
    k_ramm<<<dim3(8, 8), 256>>>(Ra, A3, 512, 1024);
    k_dinv<<<512, 256>>>(A3, 512, dinv3);

    // ---------------- down level 3, fused unpool into h2 -----
    k_featw<<<8, 256>>>(h2, dW + 3*4096, dinv3, perm2, vals, ys, 512);
    k_prop<<<16, 256>>>(A3, ys, dinv3, db + 192, h2, 512, 1, perm2);

    // ---------------- up 0: gcn over A2, fused unpool into h1
    k_featw<<<16, 256>>>(h2, uW, dinv2, nullperm, nullvals, ys, 1024);
    k_prop<<<32, 256>>>(A2, ys, dinv2, ub, h1, 1024, 1, perm1);

    // ---------------- up 1: gcn over A1, fused unpool into h0
    k_featw<<<32, 256>>>(h1, uW + 4096, dinv1, nullperm, nullvals, ys, 2048);
    k_prop_sp<<<256, 256>>>(off1, idx1, val1, ys, dinv1, ub + 64, h0, 2048, 1, perm0);

    // ---------------- up 2: gcn over adj, no relu ------------
    k_featw<<<64, 256>>>(h0, uW + 8192, dinv0, nullperm, nullvals, ys, 4096);
    k_prop_sp<<<512, 256>>>(offA, idxA, valA, ys, dinv0, ub + 128, u, 4096, 0, nullperm);

    // ---------------- final: relu, dropout(0), fc ------------
    k_final<<<512, 256>>>(u, fcw, fcb, prob, out, 4096);
}

// round 7
// speedup vs baseline: 2.2640x; 1.1419x over previous
#include <cuda_runtime.h>
#include <cuda_bf16.h>
#include <math.h>

// ---------------- static device scratch (no allocations allowed) -------------
__device__ float         g_A1[2048u*2048u];
__device__ float         g_A2[1024u*1024u];
__device__ float         g_A3[512u*512u];
__device__ float         g_Ra[512u*1024u];
__device__ __nv_bfloat16 g_Ra16[1024u*2048u];
__device__ float g_h0[4096*64];
__device__ float g_h1[2048*64];
__device__ float g_h2[1024*64];
__device__ float g_ys[4096*64];
__device__ float g_u[4096*64];
__device__ float g_dinv0[4096];
__device__ float g_dinv1[2048];
__device__ float g_dinv2[1024];
__device__ float g_dinv3[512];
__device__ int   g_perm0[2048];
__device__ int   g_perm1[1024];
__device__ int   g_perm2[512];
__device__ float g_vals[2048];
__device__ float g_score[4096];
__device__ int   g_cntA[4096];
__device__ int   g_cnt1[2048];
__device__ int   g_idxA[4096u*512u];
__device__ float g_valA[4096u*512u];
__device__ int   g_idx1[2048u*2048u];
__device__ float g_val1[2048u*2048u];
__device__ int   g_sel[4096];

#define ADJ_STRIDE 512
#define A1_STRIDE  2048

// ======= single-pass padded CSR build: idx/val/cnt (+ optional dinv) =========
__global__ void k_fillpad(const float* __restrict__ A, int n, int stride,
                          int* __restrict__ idx, float* __restrict__ val,
                          int* __restrict__ cnt, float* __restrict__ dinvOut) {
    int row = blockIdx.x * 8 + (threadIdx.x >> 5);
    int lane = threadIdx.x & 31;
    const float* a = A + (size_t)row * n;
    int* ridx = idx + (size_t)row * stride;
    float* rval = val + (size_t)row * stride;
    int ptr = 0;
    float fsum = 0.f;
    for (int j0 = 0; j0 < n; j0 += 32) {
        float v = a[j0 + lane];
        fsum += v;
        unsigned msk = __ballot_sync(0xffffffffu, v != 0.f);
        if (v != 0.f) {
            int p = ptr + __popc(msk & ((1u << lane) - 1u));
            if (p < stride) { ridx[p] = j0 + lane; rval[p] = v; }
        }
        ptr += __popc(msk);
    }
    for (int o = 16; o; o >>= 1) fsum += __shfl_xor_sync(0xffffffffu, fsum, o);
    if (lane == 0) {
        cnt[row] = (ptr < stride) ? ptr : stride;
        if (dinvOut != 0) dinvOut[row] = 1.0f / sqrtf(fsum + 2.0f);
    }
}

// ---------------- dinv[i] = 1/sqrt(rowsum(A)+2) (dense, weighted) ------------
__global__ void k_dinv(const float* __restrict__ A, int n, float* __restrict__ dinv) {
    int row = blockIdx.x;
    const float* a = A + (size_t)row * n;
    float s = 0.f;
    for (int j = threadIdx.x; j < n; j += blockDim.x) s += a[j];
    for (int o = 16; o; o >>= 1) s += __shfl_xor_sync(0xffffffffu, s, o);
    __shared__ float red[8];
    int lane = threadIdx.x & 31;
    int warp = threadIdx.x >> 5;
    if (lane == 0) red[warp] = s;
    __syncthreads();
    if (threadIdx.x == 0) {
        float t = 0.f;
        #pragma unroll
        for (int w = 0; w < 8; w++) t += red[w];
        dinv[row] = 1.0f / sqrtf(t + 2.0f);
    }
}

// ---------------- ys = dinv .* ((gather(X)) @ W), 512 threads ----------------
__global__ void __launch_bounds__(512) k_featw(const float* __restrict__ X,
                        const float* __restrict__ W,
                        const float* __restrict__ dinv, const int* __restrict__ perm,
                        const float* __restrict__ vals, float* __restrict__ ys, int n) {
    __shared__ float Ws[64][64];   // [k][c]
    __shared__ float Xs[64][65];   // [r][k]
    int tid = threadIdx.x; // 512
    int rowb = blockIdx.x * 64;
    const float4* W4 = (const float4*)W;
    float4* Ws4 = (float4*)&Ws[0][0];
    for (int i = tid; i < 1024; i += 512) Ws4[i] = W4[i];
    for (int i = tid; i < 1024; i += 512) {
        int r = i >> 4;
        int c4 = (i & 15) << 2;
        int rs = rowb + r;
        const float* src;
        float scale = 1.f;
        if (perm != 0) { src = X + (size_t)perm[rs] * 64; scale = vals[rs]; }
        else           { src = X + (size_t)rs * 64; }
        float4 v = *(const float4*)(src + c4);
        Xs[r][c4+0] = v.x * scale;
        Xs[r][c4+1] = v.y * scale;
        Xs[r][c4+2] = v.z * scale;
        Xs[r][c4+3] = v.w * scale;
    }
    __syncthreads();
    int tx = tid & 15;      // col group (4 cols)
    int ty = tid >> 4;      // 0..31 -> 2 rows each
    float4 acc0 = make_float4(0.f, 0.f, 0.f, 0.f);
    float4 acc1 = make_float4(0.f, 0.f, 0.f, 0.f);
    #pragma unroll 8
    for (int k = 0; k < 64; k++) {
        float4 b = *(float4*)&Ws[k][tx * 4];
        float a0 = Xs[ty*2+0][k];
        float a1 = Xs[ty*2+1][k];
        acc0.x += a0*b.x; acc0.y += a0*b.y; acc0.z += a0*b.z; acc0.w += a0*b.w;
        acc1.x += a1*b.x; acc1.y += a1*b.y; acc1.z += a1*b.z; acc1.w += a1*b.w;
    }
    int r0 = rowb + ty*2;
    float d0 = dinv[r0];
    float d1 = dinv[r0 + 1];
    float4 o0 = make_float4(acc0.x*d0, acc0.y*d0, acc0.z*d0, acc0.w*d0);
    float4 o1 = make_float4(acc1.x*d1, acc1.y*d1, acc1.z*d1, acc1.w*d1);
    *(float4*)(ys + (size_t)r0 * 64 + tx * 4) = o0;
    *(float4*)(ys + (size_t)(r0 + 1) * 64 + tx * 4) = o1;
}

// ---- padded sparse prop: v = act(d*(A@ys) + 2d*ys + b) ----------------------
__global__ void k_prop_sp(const int* __restrict__ idx, const float* __restrict__ val,
                          const int* __restrict__ cnt, int stride,
                          const float* __restrict__ ys,
                          const float* __restrict__ dinv, const float* __restrict__ bias,
                          float* __restrict__ h, int n, int relu,
                          const int* __restrict__ permOut) {
    int row = blockIdx.x * 8 + (threadIdx.x >> 5);
    int lane = threadIdx.x & 31;
    if (row >= n) return;
    const int* ridx = idx + (size_t)row * stride;
    const float* rval = val + (size_t)row * stride;
    int e = cnt[row];
    float a0 = 0.f;
    float a1 = 0.f;
    for (int m = 0; m < e; m++) {
        int j = ridx[m];
        float w = rval[m];
        a0 += w * ys[(size_t)j * 64 + lane];
        a1 += w * ys[(size_t)j * 64 + 32 + lane];
    }
    float d = dinv[row];
    float v0 = d * a0 + 2.f * d * ys[(size_t)row * 64 + lane] + bias[lane];
    float v1 = d * a1 + 2.f * d * ys[(size_t)row * 64 + 32 + lane] + bias[32 + lane];
    if (relu) { v0 = fmaxf(v0, 0.f); v1 = fmaxf(v1, 0.f); }
    if (permOut != 0) {
        float* dst = h + (size_t)permOut[row] * 64;
        dst[lane] += v0;
        dst[32 + lane] += v1;
    } else {
        h[(size_t)row * 64 + lane] = v0;
        h[(size_t)row * 64 + 32 + lane] = v1;
    }
}

// ---------------- dense prop -------------------------------------------------
__global__ void k_prop(const float* __restrict__ A, const float* __restrict__ ys,
                       const float* __restrict__ dinv, const float* __restrict__ bias,
                       float* __restrict__ hout, int n, int relu,
                       const int* __restrict__ permOut) {
    __shared__ float sA[32][33];
    __shared__ float sB[32][64];
    int tid = threadIdx.x; // 256
    int tx = tid & 15;
    int ty = tid >> 4;
    int rowb = blockIdx.x * 32;
    float acc[2][4] = {{0.f,0.f,0.f,0.f},{0.f,0.f,0.f,0.f}};
    for (int kb = 0; kb < n; kb += 32) {
        int r0 = tid >> 3;
        int c0 = (tid & 7) * 4;
        float4 v = *(const float4*)(A + (size_t)(rowb + r0) * n + kb + c0);
        sA[r0][c0] = v.x; sA[r0][c0+1] = v.y; sA[r0][c0+2] = v.z; sA[r0][c0+3] = v.w;
        for (int q = tid; q < 512; q += 256) {
            int r = q >> 4;
            int c4 = (q & 15) * 4;
            *(float4*)&sB[r][c4] = *(const float4*)(ys + (size_t)(kb + r) * 64 + c4);
        }
        __syncthreads();
        #pragma unroll
        for (int kk = 0; kk < 32; kk++) {
            float a0 = sA[ty*2+0][kk];
            float a1 = sA[ty*2+1][kk];
            float4 b = *(float4*)&sB[kk][tx*4];
            acc[0][0] += a0*b.x; acc[0][1] += a0*b.y; acc[0][2] += a0*b.z; acc[0][3] += a0*b.w;
            acc[1][0] += a1*b.x; acc[1][1] += a1*b.y; acc[1][2] += a1*b.z; acc[1][3] += a1*b.w;
        }
        __syncthreads();
    }
    #pragma unroll
    for (int i = 0; i < 2; i++) {
        int r = rowb + ty*2 + i;
        float d = dinv[r];
        int orow = (permOut != 0) ? permOut[r] : r;
        #pragma unroll
        for (int j = 0; j < 4; j++) {
            int c = tx*4 + j;
            float v = d*acc[i][j] + 2.f*d*ys[(size_t)r*64 + c] + bias[c];
            if (relu) v = fmaxf(v, 0.f);
            if (permOut != 0) hout[(size_t)orow*64 + c] += v;
            else              hout[(size_t)orow*64 + c] = v;
        }
    }
}

// ---------------- score (pnorm folded in, deterministic) ---------------------
__global__ void k_score(const float* __restrict__ h, const float* __restrict__ p,
                        float* __restrict__ score, int n) {
    int gw = (blockIdx.x * blockDim.x + threadIdx.x) >> 5;
    int lane = threadIdx.x & 31;
    if (gw >= n) return;
    float pl = p[lane];
    float ph = p[32 + lane];
    float pn = pl*pl + ph*ph;
    float d = h[(size_t)gw*64 + lane] * pl + h[(size_t)gw*64 + 32 + lane] * ph;
    for (int o = 16; o; o >>= 1) {
        d  += __shfl_xor_sync(0xffffffffu, d, o);
        pn += __shfl_xor_sync(0xffffffffu, pn, o);
    }
    if (lane == 0) score[gw] = tanhf(d * (1.0f / sqrtf(pn)));
}

// -------- packed-key bitonic topk (desc score, asc idx); writes sel ----------
__global__ void k_topk(const float* __restrict__ score, int n, int k,
                       int* __restrict__ perm, float* __restrict__ vals,
                       int* __restrict__ sel) {
    __shared__ unsigned long long key[4096];
    int t = threadIdx.x; // 1024
    for (int i = t; i < n; i += 1024) {
        unsigned b = __float_as_uint(score[i]);
        b = (b & 0x80000000u) ? (b ^ 0xFFFFFFFFu) : (b ^ 0x80000000u);
        key[i] = ((unsigned long long)b << 32) | (unsigned)(~i);
    }
    __syncthreads();
    for (int kk = 2; kk <= n; kk <<= 1) {
        for (int j = kk >> 1; j > 0; j >>= 1) {
            for (int i = t; i < n; i += 1024) {
                int ixj = i ^ j;
                if (ixj > i) {
                    unsigned long long k1 = key[i];
                    unsigned long long k2 = key[ixj];
                    bool dir = ((i & kk) == 0);            // descending segment
                    bool sw = dir ? (k2 > k1) : (k2 < k1);
                    if (sw) { key[i] = k2; key[ixj] = k1; }
                }
            }
            __syncthreads();
        }
    }
    for (int i = t; i < n; i += 1024) {
        int idx = (int)(~(unsigned)key[i]);
        if (i < k) {
            perm[i] = idx;
            vals[i] = score[idx];
            if (sel != 0) sel[idx] = i;
        } else {
            if (sel != 0) sel[idx] = -1;
        }
    }
}

// ---------------- pair-count augment: exact A1 in one pass -------------------
__global__ void k_pair(const int* __restrict__ idx, const int* __restrict__ cnt,
                       int stride, const int* __restrict__ sel,
                       float* __restrict__ A1, int n, int k1) {
    __shared__ int lists[8][128];
    int warp = threadIdx.x >> 5;
    int lane = threadIdx.x & 31;
    int j = blockIdx.x * 8 + warp;
    int* lst = lists[warp];
    const int* ridx = idx + (size_t)j * stride;
    int e = cnt[j];
    int total = e + 1; // + self-loop
    int c = 0;
    for (int t0 = 0; t0 < total; t0 += 32) {
        int m = t0 + lane;
        int a = -1;
        if (m < total) {
            int u = (m < total - 1) ? ridx[m] : j;
            a = sel[u];
        }
        unsigned msk = __ballot_sync(0xffffffffu, a >= 0);
        if (a >= 0) lst[c + __popc(msk & ((1u << lane) - 1u))] = a;
        c += __popc(msk);
    }
    __syncwarp();
    for (int p = lane; p < c * c; p += 32) {
        int a = p / c;
        int b = p - a * c;
        if (a != b) atomicAdd(&A1[(size_t)lst[a] * k1 + lst[b]], 1.0f);
    }
}

// ---------------- Ra gathers --------------------------------------------------
__global__ void k_gather_ra(const float* __restrict__ A, const int* __restrict__ perm,
                            float* __restrict__ Ra, int k, int m) {
    int idx = blockIdx.x * blockDim.x + threadIdx.x;
    if (idx >= k * m) return;
    int a = idx / m;
    int j = idx - a * m;
    int pa = perm[a];
    float v = A[(size_t)pa * m + j];
    if (j == pa) v += 1.f;
    Ra[idx] = v;
}

__global__ void k_gather_ra16(const float* __restrict__ A, const int* __restrict__ perm,
                              __nv_bfloat16* __restrict__ Ra, int k, int m) {
    int idx = blockIdx.x * blockDim.x + threadIdx.x;
    if (idx >= k * m) return;
    int a = idx / m;
    int j = idx - a * m;
    int pa = perm[a];
    float v = A[(size_t)pa * m + j];
    if (j == pa) v += 1.f;
    Ra[idx] = __float2bfloat16(v); // exact: small integers
}

// ---------------- fp32 ramm (level 2) ----------------------------------------
__global__ void k_ramm(const float* __restrict__ Ra, float* __restrict__ C, int k, int m) {
    __shared__ float sA[64][33];
    __shared__ float sB[64][33];
    int tid = threadIdx.x; // 256
    int tx = tid & 15;
    int ty = tid >> 4;
    int rb = blockIdx.x * 64;
    int cb = blockIdx.y * 64;
    float acc[4][4];
    #pragma unroll
    for (int i = 0; i < 4; i++) {
        #pragma unroll
        for (int j = 0; j < 4; j++) acc[i][j] = 0.f;
    }
    for (int kb = 0; kb < m; kb += 32) {
        for (int q = tid; q < 512; q += 256) {
            int r = q >> 3;
            int c4 = (q & 7) * 4;
            float4 v = *(const float4*)(Ra + (size_t)(rb + r) * m + kb + c4);
            sA[r][c4] = v.x; sA[r][c4+1] = v.y; sA[r][c4+2] = v.z; sA[r][c4+3] = v.w;
            float4 u = *(const float4*)(Ra + (size_t)(cb + r) * m + kb + c4);
            sB[r][c4] = u.x; sB[r][c4+1] = u.y; sB[r][c4+2] = u.z; sB[r][c4+3] = u.w;
        }
        __syncthreads();
        #pragma unroll
        for (int w = 0; w < 32; w++) {
            float a0 = sA[ty*4+0][w];
            float a1 = sA[ty*4+1][w];
            float a2 = sA[ty*4+2][w];
            float a3 = sA[ty*4+3][w];
            float b0 = sB[tx*4+0][w];
            float b1 = sB[tx*4+1][w];
            float b2 = sB[tx*4+2][w];
            float b3 = sB[tx*4+3][w];
            acc[0][0] += a0*b0; acc[0][1] += a0*b1; acc[0][2] += a0*b2; acc[0][3] += a0*b3;
            acc[1][0] += a1*b0; acc[1][1] += a1*b1; acc[1][2] += a1*b2; acc[1][3] += a1*b3;
            acc[2][0] += a2*b0; acc[2][1] += a2*b1; acc[2][2] += a2*b2; acc[2][3] += a2*b3;
            acc[3][0] += a3*b0; acc[3][1] += a3*b1; acc[3][2] += a3*b2; acc[3][3] += a3*b3;
        }
        __syncthreads();
    }
    #pragma unroll
    for (int i = 0; i < 4; i++) {
        int gr = rb + ty*4 + i;
        #pragma unroll
        for (int j = 0; j < 4; j++) {
            int gc = cb + tx*4 + j;
            C[(size_t)gr * k + gc] = (gr == gc) ? 0.f : acc[i][j];
        }
    }
}

// ---------------- bf16 mma.sync ramm (level 1): C = Ra @ Ra^T, exact ---------
__global__ void __launch_bounds__(128) k_ramm_mma(const __nv_bfloat16* __restrict__ Ra,
                                                  float* __restrict__ C, int k, int m) {
    int w = threadIdx.x >> 5;  // warp 0..3, each does a 16-row band
    int l = threadIdx.x & 31;
    int rb = blockIdx.x * 64 + w * 16;
    int cb = blockIdx.y * 64;
    int lr = l >> 2;   // 0..7
    int lc = l & 3;    // 0..3
    float acc[8][4];
    #pragma unroll
    for (int t = 0; t < 8; t++) {
        #pragma unroll
        for (int j = 0; j < 4; j++) acc[t][j] = 0.f;
    }
    const __nv_bfloat16* Abase = Ra + (size_t)(rb + lr) * m + lc * 2;
    const __nv_bfloat16* Bbase = Ra + (size_t)(cb + lr) * m + lc * 2;
    for (int kb = 0; kb < m; kb += 16) {
        unsigned a0 = *(const unsigned*)(Abase + kb);
        unsigned a1 = *(const unsigned*)(Abase + (size_t)8 * m + kb);
        unsigned a2 = *(const unsigned*)(Abase + kb + 8);
        unsigned a3 = *(const unsigned*)(Abase + (size_t)8 * m + kb + 8);
        #pragma unroll
        for (int t = 0; t < 8; t++) {
            unsigned b0 = *(const unsigned*)(Bbase + (size_t)t * 8 * m + kb);
            unsigned b1 = *(const unsigned*)(Bbase + (size_t)t * 8 * m + kb + 8);
            asm volatile(
                "mma.sync.aligned.m16n8k16.row.col.f32.bf16.bf16.f32 "
                "{%0,%1,%2,%3}, {%4,%5,%6,%7}, {%8,%9}, {%0,%1,%2,%3};"
                : "+f"(acc[t][0]), "+f"(acc[t][1]), "+f"(acc[t][2]), "+f"(acc[t][3])
                : "r"(a0), "r"(a1), "r"(a2), "r"(a3), "r"(b0), "r"(b1));
        }
    }
    #pragma unroll
    for (int t = 0; t < 8; t++) {
        int row0 = rb + lr;
        int row1 = rb + lr + 8;
        int col = cb + t * 8 + lc * 2;
        float v0 = (row0 == col)     ? 0.f : acc[t][0];
        float v1 = (row0 == col + 1) ? 0.f : acc[t][1];
        float v2 = (row1 == col)     ? 0.f : acc[t][2];
        float v3 = (row1 == col + 1) ? 0.f : acc[t][3];
        *(float2*)&C[(size_t)row0 * k + col] = make_float2(v0, v1);
        *(float2*)&C[(size_t)row1 * k + col] = make_float2(v2, v3);
    }
}

// ---------------- final: relu, dropout(0), fc --------------------------------
__global__ void k_final(const float* __restrict__ g, const float* __restrict__ fcw,
                        const float* __restrict__ fcb, const float* __restrict__ prob,
                        float* __restrict__ out, int n) {
    int gw = (blockIdx.x * blockDim.x + threadIdx.x) >> 5;
    int lane = threadIdx.x & 31;
    if (gw >= n) return;
    float v = fmaxf(g[(size_t)gw*64 + lane], 0.f)      * fcw[lane]
            + fmaxf(g[(size_t)gw*64 + 32 + lane], 0.f) * fcw[32 + lane];
    for (int o = 16; o; o >>= 1) v += __shfl_xor_sync(0xffffffffu, v, o);
    if (lane == 0) out[gw] = v / (1.f - prob[0]) + fcb[0];
}

// =============================================================================
extern "C" void kernel_launch(void* const* d_in, const int* in_sizes, int n_in,
                              void* d_out, int out_size) {
    (void)in_sizes;
    (void)n_in;
    (void)out_size;
    const float* x    = (const float*)d_in[0];
    const float* adj  = (const float*)d_in[1];
    const float* prob = (const float*)d_in[2];
    const float* dW   = (const float*)d_in[3];
    const float* db   = (const float*)d_in[4];
    const float* pw   = (const float*)d_in[5];
    const float* uW   = (const float*)d_in[6];
    const float* ub   = (const float*)d_in[7];
    const float* fcw  = (const float*)d_in[8];
    const float* fcb  = (const float*)d_in[9];
    float* out = (float*)d_out;

    void* pv;
    cudaGetSymbolAddress(&pv, g_A1);    float* A1 = (float*)pv;
    cudaGetSymbolAddress(&pv, g_A2);    float* A2 = (float*)pv;
    cudaGetSymbolAddress(&pv, g_A3);    float* A3 = (float*)pv;
    cudaGetSymbolAddress(&pv, g_Ra);    float* Ra = (float*)pv;
    cudaGetSymbolAddress(&pv, g_Ra16);  __nv_bfloat16* Ra16 = (__nv_bfloat16*)pv;
    cudaGetSymbolAddress(&pv, g_h0);    float* h0 = (float*)pv;
    cudaGetSymbolAddress(&pv, g_h1);    float* h1 = (float*)pv;
    cudaGetSymbolAddress(&pv, g_h2);    float* h2 = (float*)pv;
    cudaGetSymbolAddress(&pv, g_ys);    float* ys = (float*)pv;
    cudaGetSymbolAddress(&pv, g_u);     float* u  = (float*)pv;
    cudaGetSymbolAddress(&pv, g_dinv0); float* dinv0 = (float*)pv;
    cudaGetSymbolAddress(&pv, g_dinv1); float* dinv1 = (float*)pv;
    cudaGetSymbolAddress(&pv, g_dinv2); float* dinv2 = (float*)pv;
    cudaGetSymbolAddress(&pv, g_dinv3); float* dinv3 = (float*)pv;
    cudaGetSymbolAddress(&pv, g_perm0); int* perm0 = (int*)pv;
    cudaGetSymbolAddress(&pv, g_perm1); int* perm1 = (int*)pv;
    cudaGetSymbolAddress(&pv, g_perm2); int* perm2 = (int*)pv;
    cudaGetSymbolAddress(&pv, g_vals);  float* vals = (float*)pv;
    cudaGetSymbolAddress(&pv, g_score); float* score = (float*)pv;
    cudaGetSymbolAddress(&pv, g_cntA);  int* cntA = (int*)pv;
    cudaGetSymbolAddress(&pv, g_cnt1);  int* cnt1 = (int*)pv;
    cudaGetSymbolAddress(&pv, g_idxA);  int* idxA = (int*)pv;
    cudaGetSymbolAddress(&pv, g_valA);  float* valA = (float*)pv;
    cudaGetSymbolAddress(&pv, g_idx1);  int* idx1 = (int*)pv;
    cudaGetSymbolAddress(&pv, g_val1);  float* val1 = (float*)pv;
    cudaGetSymbolAddress(&pv, g_sel);   int* sel  = (int*)pv;

    const int* nullperm = (const int*)0;
    const float* nullvals = (const float*)0;

    // ------- CSR(adj) + dinv0 in one pass --------------------
    k_fillpad<<<512, 256>>>(adj, 4096, ADJ_STRIDE, idxA, valA, cntA, dinv0);

    // ------- down level 0 (n = 4096) -------------------------
    k_featw<<<64, 512>>>(x, dW, dinv0, nullperm, nullvals, ys, 4096);
    k_prop_sp<<<512, 256>>>(idxA, valA, cntA, ADJ_STRIDE, ys, dinv0, db, h0, 4096, 1, nullperm);

    // ------- pool 0: 4096 -> 2048 ----------------------------
    k_score<<<512, 256>>>(h0, pw, score, 4096);
    k_topk<<<1, 1024>>>(score, 4096, 2048, perm0, vals, sel);
    cudaMemsetAsync(A1, 0, (size_t)2048*2048*sizeof(float));
    k_pair<<<512, 256>>>(idxA, cntA, ADJ_STRIDE, sel, A1, 4096, 2048);
    k_fillpad<<<256, 256>>>(A1, 2048, A1_STRIDE, idx1, val1, cnt1, dinv1);

    // ------- down level 1 ------------------------------------
    k_featw<<<32, 512>>>(h0, dW + 1*4096, dinv1, perm0, vals, ys, 2048);
    k_prop_sp<<<256, 256>>>(idx1, val1, cnt1, A1_STRIDE, ys, dinv1, db + 64, h1, 2048, 1, nullperm);

    // ------- pool 1: 2048 -> 1024 ----------------------------
    k_score<<<256, 256>>>(h1, pw + 64, score, 2048);
    k_topk<<<1, 1024>>>(score, 2048, 1024, perm1, vals, (int*)0);
    k_gather_ra16<<<8192, 256>>>(A1, perm1, Ra16, 1024, 2048);
    k_ramm_mma<<<dim3(16, 16), 128>>>(Ra16, A2, 1024, 2048);
    k_dinv<<<1024, 256>>>(A2, 1024, dinv2);

    // ------- down level 2 ------------------------------------
    k_featw<<<16, 512>>>(h1, dW + 2*4096, dinv2, perm1, vals, ys, 1024);
    k_prop<<<32, 256>>>(A2, ys, dinv2, db + 128, h2, 1024, 1, nullperm);

    // ------- pool 2: 1024 -> 512 -----------------------------
    k_score<<<128, 256>>>(h2, pw + 128, score, 1024);
    k_topk<<<1, 1024>>>(score, 1024, 512, perm2, vals, (int*)0);
    k_gather_ra<<<2048, 256>>>(A2, perm2, Ra, 512, 1024);
    k_ramm<<<dim3(8, 8), 256>>>(Ra, A3, 512, 1024);
    k_dinv<<<512, 256>>>(A3, 512, dinv3);

    // ------- down level 3, fused unpool into h2 --------------
    k_featw<<<8, 512>>>(h2, dW + 3*4096, dinv3, perm2, vals, ys, 512);
    k_prop<<<16, 256>>>(A3, ys, dinv3, db + 192, h2, 512, 1, perm2);

    // ------- up 0: gcn over A2, fused unpool into h1 ---------
    k_featw<<<16, 512>>>(h2, uW, dinv2, nullperm, nullvals, ys, 1024);
    k_prop<<<32, 256>>>(A2, ys, dinv2, ub, h1, 1024, 1, perm1);

    // ------- up 1: gcn over A1, fused unpool into h0 ---------
    k_featw<<<32, 512>>>(h1, uW + 4096, dinv1, nullperm, nullvals, ys, 2048);
    k_prop_sp<<<256, 256>>>(idx1, val1, cnt1, A1_STRIDE, ys, dinv1, ub + 64, h0, 2048, 1, perm0);

    // ------- up 2: gcn over adj, no relu ---------------------
    k_featw<<<64, 512>>>(h0, uW + 8192, dinv0, nullperm, nullvals, ys, 4096);
    k_prop_sp<<<512, 256>>>(idxA, valA, cntA, ADJ_STRIDE, ys, dinv0, ub + 128, u, 4096, 0, nullperm);

    // ------- final: relu, dropout(0), fc ---------------------
    k_final<<<512, 256>>>(u, fcw, fcb, prob, out, 4096);
}

// round 8
// speedup vs baseline: 2.3197x; 1.0246x over previous
#include <cuda_runtime.h>
#include <cuda_bf16.h>
#include <math.h>

// ---------------- static device scratch (no allocations allowed) -------------
__device__ __nv_bfloat16 g_A1b[2048u*2048u];
__device__ float g_A2[1024u*1024u];
__device__ float g_A3[512u*512u];
__device__ float g_h0[4096*64];
__device__ float g_h1[2048*64];
__device__ float g_h2[1024*64];
__device__ float g_ys[4096*64];
__device__ float g_u[4096*64];
__device__ float g_dinv0[4096];
__device__ float g_dinv1[2048];
__device__ float g_dinv2[1024];
__device__ float g_dinv3[512];
__device__ float g_sums2[1024];
__device__ int   g_perm0[2048];
__device__ int   g_perm1[1024];
__device__ int   g_perm2[512];
__device__ float g_vals[2048];
__device__ float g_score[4096];
__device__ int   g_cntA[4096];
__device__ int   g_cnt1[2048];
__device__ int   g_idxA[4096u*512u];
__device__ float g_valA[4096u*512u];
__device__ int   g_idx1[2048u*2048u];
__device__ float g_val1[2048u*2048u];
__device__ int   g_sel[4096];

#define ADJ_STRIDE 512
#define A1_STRIDE  2048

// ======= single-pass padded CSR build (adj) + dinv ===========================
__global__ void k_fillpad(const float* __restrict__ A, int n, int stride,
                          int* __restrict__ idx, float* __restrict__ val,
                          int* __restrict__ cnt, float* __restrict__ dinvOut) {
    int row = blockIdx.x * 8 + (threadIdx.x >> 5);
    int lane = threadIdx.x & 31;
    const float* a = A + (size_t)row * n;
    int* ridx = idx + (size_t)row * stride;
    float* rval = val + (size_t)row * stride;
    int ptr = 0;
    float fsum = 0.f;
    for (int j0 = 0; j0 < n; j0 += 32) {
        float v = a[j0 + lane];
        fsum += v;
        unsigned msk = __ballot_sync(0xffffffffu, v != 0.f);
        if (v != 0.f) {
            int p = ptr + __popc(msk & ((1u << lane) - 1u));
            if (p < stride) { ridx[p] = j0 + lane; rval[p] = v; }
        }
        ptr += __popc(msk);
    }
    for (int o = 16; o; o >>= 1) fsum += __shfl_xor_sync(0xffffffffu, fsum, o);
    if (lane == 0) {
        cnt[row] = (ptr < stride) ? ptr : stride;
        if (dinvOut != 0) dinvOut[row] = 1.0f / sqrtf(fsum + 2.0f);
    }
}

// ---------------- dinv[i] = 1/sqrt(rowsum(A)+2) (dense) ----------------------
__global__ void k_dinv(const float* __restrict__ A, int n, float* __restrict__ dinv) {
    int row = blockIdx.x;
    const float* a = A + (size_t)row * n;
    float s = 0.f;
    for (int j = threadIdx.x; j < n; j += blockDim.x) s += a[j];
    for (int o = 16; o; o >>= 1) s += __shfl_xor_sync(0xffffffffu, s, o);
    __shared__ float red[8];
    int lane = threadIdx.x & 31;
    int warp = threadIdx.x >> 5;
    if (lane == 0) red[warp] = s;
    __syncthreads();
    if (threadIdx.x == 0) {
        float t = 0.f;
        #pragma unroll
        for (int w = 0; w < 8; w++) t += red[w];
        dinv[row] = 1.0f / sqrtf(t + 2.0f);
    }
}

// --------- ys = d .* ((gather(X)) @ W); d from dinvIn or rsqrt(sums+2) -------
__global__ void __launch_bounds__(512) k_featw(const float* __restrict__ X,
                        const float* __restrict__ W,
                        const float* __restrict__ dinvIn, const float* __restrict__ sums,
                        float* __restrict__ dinvOut,
                        const int* __restrict__ perm, const float* __restrict__ vals,
                        float* __restrict__ ys, int n) {
    __shared__ float Ws[64][64];
    __shared__ float Xs[64][65];
    int tid = threadIdx.x; // 512
    int rowb = blockIdx.x * 64;
    const float4* W4 = (const float4*)W;
    float4* Ws4 = (float4*)&Ws[0][0];
    for (int i = tid; i < 1024; i += 512) Ws4[i] = W4[i];
    for (int i = tid; i < 1024; i += 512) {
        int r = i >> 4;
        int c4 = (i & 15) << 2;
        int rs = rowb + r;
        const float* src;
        float scale = 1.f;
        if (perm != 0) { src = X + (size_t)perm[rs] * 64; scale = vals[rs]; }
        else           { src = X + (size_t)rs * 64; }
        float4 v = *(const float4*)(src + c4);
        Xs[r][c4+0] = v.x * scale;
        Xs[r][c4+1] = v.y * scale;
        Xs[r][c4+2] = v.z * scale;
        Xs[r][c4+3] = v.w * scale;
    }
    __syncthreads();
    int tx = tid & 15;
    int ty = tid >> 4;
    float4 acc0 = make_float4(0.f, 0.f, 0.f, 0.f);
    float4 acc1 = make_float4(0.f, 0.f, 0.f, 0.f);
    #pragma unroll 8
    for (int k = 0; k < 64; k++) {
        float4 b = *(float4*)&Ws[k][tx * 4];
        float a0 = Xs[ty*2+0][k];
        float a1 = Xs[ty*2+1][k];
        acc0.x += a0*b.x; acc0.y += a0*b.y; acc0.z += a0*b.z; acc0.w += a0*b.w;
        acc1.x += a1*b.x; acc1.y += a1*b.y; acc1.z += a1*b.z; acc1.w += a1*b.w;
    }
    int r0 = rowb + ty*2;
    float d0, d1;
    if (sums != 0) {
        d0 = 1.0f / sqrtf(sums[r0] + 2.0f);
        d1 = 1.0f / sqrtf(sums[r0 + 1] + 2.0f);
    } else {
        d0 = dinvIn[r0];
        d1 = dinvIn[r0 + 1];
    }
    if (dinvOut != 0 && tx == 0) { dinvOut[r0] = d0; dinvOut[r0 + 1] = d1; }
    float4 o0 = make_float4(acc0.x*d0, acc0.y*d0, acc0.z*d0, acc0.w*d0);
    float4 o1 = make_float4(acc1.x*d1, acc1.y*d1, acc1.z*d1, acc1.w*d1);
    *(float4*)(ys + (size_t)r0 * 64 + tx * 4) = o0;
    *(float4*)(ys + (size_t)(r0 + 1) * 64 + tx * 4) = o1;
}

// ---- padded sparse prop (+ optional fused score, optional scatter-out) ------
__global__ void k_prop_sp(const int* __restrict__ idx, const float* __restrict__ val,
                          const int* __restrict__ cnt, int stride,
                          const float* __restrict__ ys,
                          const float* __restrict__ dinv, const float* __restrict__ bias,
                          float* __restrict__ h, int n, int relu,
                          const int* __restrict__ permOut,
                          const float* __restrict__ pw, float* __restrict__ scoreOut) {
    int row = blockIdx.x * 8 + (threadIdx.x >> 5);
    int lane = threadIdx.x & 31;
    if (row >= n) return;
    const int* ridx = idx + (size_t)row * stride;
    const float* rval = val + (size_t)row * stride;
    int e = cnt[row];
    float a0 = 0.f;
    float a1 = 0.f;
    for (int m = 0; m < e; m++) {
        int j = ridx[m];
        float w = rval[m];
        a0 += w * ys[(size_t)j * 64 + lane];
        a1 += w * ys[(size_t)j * 64 + 32 + lane];
    }
    float d = dinv[row];
    float v0 = d * a0 + 2.f * d * ys[(size_t)row * 64 + lane] + bias[lane];
    float v1 = d * a1 + 2.f * d * ys[(size_t)row * 64 + 32 + lane] + bias[32 + lane];
    if (relu) { v0 = fmaxf(v0, 0.f); v1 = fmaxf(v1, 0.f); }
    if (permOut != 0) {
        float* dst = h + (size_t)permOut[row] * 64;
        dst[lane] += v0;
        dst[32 + lane] += v1;
    } else {
        h[(size_t)row * 64 + lane] = v0;
        h[(size_t)row * 64 + 32 + lane] = v1;
    }
    if (scoreOut != 0) {
        float pl = pw[lane];
        float ph = pw[32 + lane];
        float pn = pl*pl + ph*ph;
        float dd = v0 * pl + v1 * ph;
        for (int o = 16; o; o >>= 1) {
            dd += __shfl_xor_sync(0xffffffffu, dd, o);
            pn += __shfl_xor_sync(0xffffffffu, pn, o);
        }
        if (lane == 0) scoreOut[row] = tanhf(dd * (1.0f / sqrtf(pn)));
    }
}

// ---------------- dense prop -------------------------------------------------
__global__ void k_prop(const float* __restrict__ A, const float* __restrict__ ys,
                       const float* __restrict__ dinv, const float* __restrict__ bias,
                       float* __restrict__ hout, int n, int relu,
                       const int* __restrict__ permOut) {
    __shared__ float sA[32][33];
    __shared__ float sB[32][64];
    int tid = threadIdx.x; // 256
    int tx = tid & 15;
    int ty = tid >> 4;
    int rowb = blockIdx.x * 32;
    float acc[2][4] = {{0.f,0.f,0.f,0.f},{0.f,0.f,0.f,0.f}};
    for (int kb = 0; kb < n; kb += 32) {
        int r0 = tid >> 3;
        int c0 = (tid & 7) * 4;
        float4 v = *(const float4*)(A + (size_t)(rowb + r0) * n + kb + c0);
        sA[r0][c0] = v.x; sA[r0][c0+1] = v.y; sA[r0][c0+2] = v.z; sA[r0][c0+3] = v.w;
        for (int q = tid; q < 512; q += 256) {
            int r = q >> 4;
            int c4 = (q & 15) * 4;
            *(float4*)&sB[r][c4] = *(const float4*)(ys + (size_t)(kb + r) * 64 + c4);
        }
        __syncthreads();
        #pragma unroll
        for (int kk = 0; kk < 32; kk++) {
            float a0 = sA[ty*2+0][kk];
            float a1 = sA[ty*2+1][kk];
            float4 b = *(float4*)&sB[kk][tx*4];
            acc[0][0] += a0*b.x; acc[0][1] += a0*b.y; acc[0][2] += a0*b.z; acc[0][3] += a0*b.w;
            acc[1][0] += a1*b.x; acc[1][1] += a1*b.y; acc[1][2] += a1*b.z; acc[1][3] += a1*b.w;
        }
        __syncthreads();
    }
    #pragma unroll
    for (int i = 0; i < 2; i++) {
        int r = rowb + ty*2 + i;
        float d = dinv[r];
        int orow = (permOut != 0) ? permOut[r] : r;
        #pragma unroll
        for (int j = 0; j < 4; j++) {
            int c = tx*4 + j;
            float v = d*acc[i][j] + 2.f*d*ys[(size_t)r*64 + c] + bias[c];
            if (relu) v = fmaxf(v, 0.f);
            if (permOut != 0) hout[(size_t)orow*64 + c] += v;
            else              hout[(size_t)orow*64 + c] = v;
        }
    }
}

// ---------------- standalone score (level 2 only) ----------------------------
__global__ void k_score(const float* __restrict__ h, const float* __restrict__ p,
                        float* __restrict__ score, int n) {
    int gw = (blockIdx.x * blockDim.x + threadIdx.x) >> 5;
    int lane = threadIdx.x & 31;
    if (gw >= n) return;
    float pl = p[lane];
    float ph = p[32 + lane];
    float pn = pl*pl + ph*ph;
    float d = h[(size_t)gw*64 + lane] * pl + h[(size_t)gw*64 + 32 + lane] * ph;
    for (int o = 16; o; o >>= 1) {
        d  += __shfl_xor_sync(0xffffffffu, d, o);
        pn += __shfl_xor_sync(0xffffffffu, pn, o);
    }
    if (lane == 0) score[gw] = tanhf(d * (1.0f / sqrtf(pn)));
}

// -------- packed-key bitonic topk; optional sel write, optional zeroBuf ------
__global__ void k_topk(const float* __restrict__ score, int n, int k,
                       int* __restrict__ perm, float* __restrict__ vals,
                       int* __restrict__ sel, float* __restrict__ zeroBuf) {
    __shared__ unsigned long long key[4096];
    int t = threadIdx.x; // 1024
    for (int i = t; i < n; i += 1024) {
        unsigned b = __float_as_uint(score[i]);
        b = (b & 0x80000000u) ? (b ^ 0xFFFFFFFFu) : (b ^ 0x80000000u);
        key[i] = ((unsigned long long)b << 32) | (unsigned)(~i);
    }
    __syncthreads();
    for (int kk = 2; kk <= n; kk <<= 1) {
        for (int j = kk >> 1; j > 0; j >>= 1) {
            for (int i = t; i < n; i += 1024) {
                int ixj = i ^ j;
                if (ixj > i) {
                    unsigned long long k1 = key[i];
                    unsigned long long k2 = key[ixj];
                    bool dir = ((i & kk) == 0);
                    bool sw = dir ? (k2 > k1) : (k2 < k1);
                    if (sw) { key[i] = k2; key[ixj] = k1; }
                }
            }
            __syncthreads();
        }
    }
    for (int i = t; i < n; i += 1024) {
        int idx = (int)(~(unsigned)key[i]);
        if (i < k) {
            perm[i] = idx;
            vals[i] = score[idx];
            if (sel != 0) sel[idx] = i;
            if (zeroBuf != 0) zeroBuf[i] = 0.f;
        } else {
            if (sel != 0) sel[idx] = -1;
        }
    }
}

// ------- augment row builder: A1 bf16 dense row + CSR row + dinv1 ------------
// A1[a][b] = #{ j : j in N_sl(perm0[a]) and j in N_sl(perm0[b]) }, diag = 0
__global__ void k_augrow(const int* __restrict__ idxA, const int* __restrict__ cntA,
                         const int* __restrict__ sel, const int* __restrict__ perm0,
                         __nv_bfloat16* __restrict__ A1b,
                         int* __restrict__ idx1, float* __restrict__ val1,
                         int* __restrict__ cnt1, float* __restrict__ dinv1) {
    __shared__ unsigned counts[2048];
    __shared__ int jlist[528];
    int a = blockIdx.x;
    int pa = perm0[a];
    int tid = threadIdx.x; // 256
    for (int i = tid; i < 2048; i += 256) counts[i] = 0u;
    int na = cntA[pa];
    for (int i = tid; i < na; i += 256) jlist[i] = idxA[(size_t)pa * ADJ_STRIDE + i];
    if (tid == 0) jlist[na] = pa;
    __syncthreads();
    int warp = tid >> 5;
    int lane = tid & 31;
    for (int ji = warp; ji < na + 1; ji += 8) {
        int j = jlist[ji];
        int nj = cntA[j];
        const int* rj = idxA + (size_t)j * ADJ_STRIDE;
        for (int m = lane; m < nj + 1; m += 32) {
            int uu = (m < nj) ? rj[m] : j;
            int s = sel[uu];
            if (s >= 0) atomicAdd(&counts[s], 1u);
        }
    }
    __syncthreads();
    if (tid == 0) counts[a] = 0u; // remove self loop
    __syncthreads();
    // dense bf16 row
    unsigned* dst = (unsigned*)(A1b + (size_t)a * 2048);
    for (int i = tid; i < 1024; i += 256) {
        __nv_bfloat162 pr;
        pr.x = __float2bfloat16((float)counts[2*i]);
        pr.y = __float2bfloat16((float)counts[2*i + 1]);
        dst[i] = *(unsigned*)&pr;
    }
    // CSR row + dinv by warp 0
    if (warp == 0) {
        int ptr = 0;
        float fsum = 0.f;
        int* ridx = idx1 + (size_t)a * A1_STRIDE;
        float* rval = val1 + (size_t)a * A1_STRIDE;
        for (int j0 = 0; j0 < 2048; j0 += 32) {
            unsigned c = counts[j0 + lane];
            fsum += (float)c;
            unsigned msk = __ballot_sync(0xffffffffu, c != 0u);
            if (c != 0u) {
                int p = ptr + __popc(msk & ((1u << lane) - 1u));
                ridx[p] = j0 + lane;
                rval[p] = (float)c;
            }
            ptr += __popc(msk);
        }
        for (int o = 16; o; o >>= 1) fsum += __shfl_xor_sync(0xffffffffu, fsum, o);
        if (lane == 0) {
            cnt1[a] = ptr;
            dinv1[a] = 1.0f / sqrtf(fsum + 2.0f);
        }
    }
}

// -- bf16 mma ramm with perm rows: C = dot(A[pa],A[pb]) + 2A[pa][pb]; +rowsums
__global__ void __launch_bounds__(128) k_ramm_mma_perm(const __nv_bfloat16* __restrict__ Ab,
        const int* __restrict__ perm, float* __restrict__ C, float* __restrict__ sums,
        int k, int m) {
    int w = threadIdx.x >> 5;
    int l = threadIdx.x & 31;
    int rb = blockIdx.x * 64 + w * 16;
    int cb = blockIdx.y * 64;
    int lr = l >> 2;
    int lc = l & 3;
    int ra0 = perm[rb + lr];
    int ra1 = perm[rb + lr + 8];
    int rbv[8];
    #pragma unroll
    for (int t = 0; t < 8; t++) rbv[t] = perm[cb + t*8 + lr];
    float acc[8][4];
    #pragma unroll
    for (int t = 0; t < 8; t++) {
        #pragma unroll
        for (int j = 0; j < 4; j++) acc[t][j] = 0.f;
    }
    const unsigned* A0 = (const unsigned*)(Ab + (size_t)ra0 * m) + lc;
    const unsigned* A1r = (const unsigned*)(Ab + (size_t)ra1 * m) + lc;
    for (int kb = 0; kb < m; kb += 16) {
        int kw = kb >> 1;
        unsigned a0 = A0[kw];
        unsigned a1 = A1r[kw];
        unsigned a2 = A0[kw + 4];
        unsigned a3 = A1r[kw + 4];
        #pragma unroll
        for (int t = 0; t < 8; t++) {
            const unsigned* Bp = (const unsigned*)(Ab + (size_t)rbv[t] * m) + lc;
            unsigned b0 = Bp[kw];
            unsigned b1 = Bp[kw + 4];
            asm volatile(
                "mma.sync.aligned.m16n8k16.row.col.f32.bf16.bf16.f32 "
                "{%0,%1,%2,%3}, {%4,%5,%6,%7}, {%8,%9}, {%0,%1,%2,%3};"
                : "+f"(acc[t][0]), "+f"(acc[t][1]), "+f"(acc[t][2]), "+f"(acc[t][3])
                : "r"(a0), "r"(a1), "r"(a2), "r"(a3), "r"(b0), "r"(b1));
        }
    }
    int row0 = rb + lr;
    int row1 = rb + lr + 8;
    float rs0 = 0.f;
    float rs1 = 0.f;
    #pragma unroll
    for (int t = 0; t < 8; t++) {
        int c0 = cb + t * 8 + lc * 2;
        int c1 = c0 + 1;
        int pc0 = perm[c0];
        int pc1 = perm[c1];
        float v00 = (row0 == c0) ? 0.f : acc[t][0] + 2.f * __bfloat162float(Ab[(size_t)ra0 * m + pc0]);
        float v01 = (row0 == c1) ? 0.f : acc[t][1] + 2.f * __bfloat162float(Ab[(size_t)ra0 * m + pc1]);
        float v10 = (row1 == c0) ? 0.f : acc[t][2] + 2.f * __bfloat162float(Ab[(size_t)ra1 * m + pc0]);
        float v11 = (row1 == c1) ? 0.f : acc[t][3] + 2.f * __bfloat162float(Ab[(size_t)ra1 * m + pc1]);
        *(float2*)&C[(size_t)row0 * k + c0] = make_float2(v00, v01);
        *(float2*)&C[(size_t)row1 * k + c0] = make_float2(v10, v11);
        rs0 += v00 + v01;
        rs1 += v10 + v11;
    }
    if (sums != 0) {
        atomicAdd(&sums[row0], rs0);  // integer-valued: exact, order-free
        atomicAdd(&sums[row1], rs1);
    }
}

// -- fp32 SIMT ramm with perm rows (level 2): C = dot + 2*A[pa][pb], diag 0 ---
__global__ void k_ramm_f32_perm(const float* __restrict__ A, const int* __restrict__ perm,
                                float* __restrict__ C, int k, int m) {
    __shared__ float sA[64][33];
    __shared__ float sB[64][33];
    __shared__ int prA[64];
    __shared__ int prB[64];
    int tid = threadIdx.x; // 256
    int tx = tid & 15;
    int ty = tid >> 4;
    int rb = blockIdx.x * 64;
    int cb = blockIdx.y * 64;
    if (tid < 64) prA[tid] = perm[rb + tid];
    else if (tid < 128) prB[tid - 64] = perm[cb + tid - 64];
    __syncthreads();
    float acc[4][4];
    #pragma unroll
    for (int i = 0; i < 4; i++) {
        #pragma unroll
        for (int j = 0; j < 4; j++) acc[i][j] = 0.f;
    }
    for (int kb = 0; kb < m; kb += 32) {
        for (int q = tid; q < 512; q += 256) {
            int r = q >> 3;
            int c4 = (q & 7) * 4;
            float4 v = *(const float4*)(A + (size_t)prA[r] * m + kb + c4);
            sA[r][c4] = v.x; sA[r][c4+1] = v.y; sA[r][c4+2] = v.z; sA[r][c4+3] = v.w;
            float4 u = *(const float4*)(A + (size_t)prB[r] * m + kb + c4);
            sB[r][c4] = u.x; sB[r][c4+1] = u.y; sB[r][c4+2] = u.z; sB[r][c4+3] = u.w;
        }
        __syncthreads();
        #pragma unroll
        for (int w = 0; w < 32; w++) {
            float a0 = sA[ty*4+0][w];
            float a1 = sA[ty*4+1][w];
            float a2 = sA[ty*4+2][w];
            float a3 = sA[ty*4+3][w];
            float b0 = sB[tx*4+0][w];
            float b1 = sB[tx*4+1][w];
            float b2 = sB[tx*4+2][w];
            float b3 = sB[tx*4+3][w];
            acc[0][0] += a0*b0; acc[0][1] += a0*b1; acc[0][2] += a0*b2; acc[0][3] += a0*b3;
            acc[1][0] += a1*b0; acc[1][1] += a1*b1; acc[1][2] += a1*b2; acc[1][3] += a1*b3;
            acc[2][0] += a2*b0; acc[2][1] += a2*b1; acc[2][2] += a2*b2; acc[2][3] += a2*b3;
            acc[3][0] += a3*b0; acc[3][1] += a3*b1; acc[3][2] += a3*b2; acc[3][3] += a3*b3;
        }
        __syncthreads();
    }
    #pragma unroll
    for (int i = 0; i < 4; i++) {
        int gr = rb + ty*4 + i;
        int pr = prA[ty*4 + i];
        #pragma unroll
        for (int j = 0; j < 4; j++) {
            int gc = cb + tx*4 + j;
            float v = acc[i][j] + 2.f * A[(size_t)pr * m + prB[tx*4 + j]];
            C[(size_t)gr * k + gc] = (gr == gc) ? 0.f : v;
        }
    }
}

// ---------------- final: relu, dropout(0), fc --------------------------------
__global__ void k_final(const float* __restrict__ g, const float* __restrict__ fcw,
                        const float* __restrict__ fcb, const float* __restrict__ prob,
                        float* __restrict__ out, int n) {
    int gw = (blockIdx.x * blockDim.x + threadIdx.x) >> 5;
    int lane = threadIdx.x & 31;
    if (gw >= n) return;
    float v = fmaxf(g[(size_t)gw*64 + lane], 0.f)      * fcw[lane]
            + fmaxf(g[(size_t)gw*64 + 32 + lane], 0.f) * fcw[32 + lane];
    for (int o = 16; o; o >>= 1) v += __shfl_xor_sync(0xffffffffu, v, o);
    if (lane == 0) out[gw] = v / (1.f - prob[0]) + fcb[0];
}

// =============================================================================
extern "C" void kernel_launch(void* const* d_in, const int* in_sizes, int n_in,
                              void* d_out, int out_size) {
    (void)in_sizes;
    (void)n_in;
    (void)out_size;
    const float* x    = (const float*)d_in[0];
    const float* adj  = (const float*)d_in[1];
    const float* prob = (const float*)d_in[2];
    const float* dW   = (const float*)d_in[3];
    const float* db   = (const float*)d_in[4];
    const float* pw   = (const float*)d_in[5];
    const float* uW   = (const float*)d_in[6];
    const float* ub   = (const float*)d_in[7];
    const float* fcw  = (const float*)d_in[8];
    const float* fcb  = (const float*)d_in[9];
    float* out = (float*)d_out;

    void* pv;
    cudaGetSymbolAddress(&pv, g_A1b);   __nv_bfloat16* A1b = (__nv_bfloat16*)pv;
    cudaGetSymbolAddress(&pv, g_A2);    float* A2 = (float*)pv;
    cudaGetSymbolAddress(&pv, g_A3);    float* A3 = (float*)pv;
    cudaGetSymbolAddress(&pv, g_h0);    float* h0 = (float*)pv;
    cudaGetSymbolAddress(&pv, g_h1);    float* h1 = (float*)pv;
    cudaGetSymbolAddress(&pv, g_h2);    float* h2 = (float*)pv;
    cudaGetSymbolAddress(&pv, g_ys);    float* ys = (float*)pv;
    cudaGetSymbolAddress(&pv, g_u);     float* u  = (float*)pv;
    cudaGetSymbolAddress(&pv, g_dinv0); float* dinv0 = (float*)pv;
    cudaGetSymbolAddress(&pv, g_dinv1); float* dinv1 = (float*)pv;
    cudaGetSymbolAddress(&pv, g_dinv2); float* dinv2 = (float*)pv;
    cudaGetSymbolAddress(&pv, g_dinv3); float* dinv3 = (float*)pv;
    cudaGetSymbolAddress(&pv, g_sums2); float* sums2 = (float*)pv;
    cudaGetSymbolAddress(&pv, g_perm0); int* perm0 = (int*)pv;
    cudaGetSymbolAddress(&pv, g_perm1); int* perm1 = (int*)pv;
    cudaGetSymbolAddress(&pv, g_perm2); int* perm2 = (int*)pv;
    cudaGetSymbolAddress(&pv, g_vals);  float* vals = (float*)pv;
    cudaGetSymbolAddress(&pv, g_score); float* score = (float*)pv;
    cudaGetSymbolAddress(&pv, g_cntA);  int* cntA = (int*)pv;
    cudaGetSymbolAddress(&pv, g_cnt1);  int* cnt1 = (int*)pv;
    cudaGetSymbolAddress(&pv, g_idxA);  int* idxA = (int*)pv;
    cudaGetSymbolAddress(&pv, g_valA);  float* valA = (float*)pv;
    cudaGetSymbolAddress(&pv, g_idx1);  int* idx1 = (int*)pv;
    cudaGetSymbolAddress(&pv, g_val1);  float* val1 = (float*)pv;
    cudaGetSymbolAddress(&pv, g_sel);   int* sel  = (int*)pv;

    const int* np = (const int*)0;
    const float* nv = (const float*)0;
    float* nf = (float*)0;

    // 1. CSR(adj) + dinv0
    k_fillpad<<<512, 256>>>(adj, 4096, ADJ_STRIDE, idxA, valA, cntA, dinv0);
    // 2-3. down L0 + fused score
    k_featw<<<64, 512>>>(x, dW, dinv0, nv, nf, np, nv, ys, 4096);
    k_prop_sp<<<512, 256>>>(idxA, valA, cntA, ADJ_STRIDE, ys, dinv0, db, h0, 4096, 1, np, pw, score);
    // 4. topk 4096->2048 (writes sel)
    k_topk<<<1, 1024>>>(score, 4096, 2048, perm0, vals, sel, nf);
    // 5. augment: A1 bf16 dense + CSR1 + dinv1
    k_augrow<<<2048, 256>>>(idxA, cntA, sel, perm0, A1b, idx1, val1, cnt1, dinv1);
    // 6-7. down L1 + fused score
    k_featw<<<32, 512>>>(h0, dW + 4096, dinv1, nv, nf, perm0, vals, ys, 2048);
    k_prop_sp<<<256, 256>>>(idx1, val1, cnt1, A1_STRIDE, ys, dinv1, db + 64, h1, 2048, 1, np, pw + 64, score);
    // 8. topk 2048->1024 (zeroes sums2)
    k_topk<<<1, 1024>>>(score, 2048, 1024, perm1, vals, (int*)0, sums2);
    // 9. A2 = perm-ramm(A1) via mma, + integer-exact rowsums
    k_ramm_mma_perm<<<dim3(16, 16), 128>>>(A1b, perm1, A2, sums2, 1024, 2048);
    // 10-11. down L2 (dinv2 from sums2, written for later reuse)
    k_featw<<<16, 512>>>(h1, dW + 8192, nv, sums2, dinv2, perm1, vals, ys, 1024);
    k_prop<<<32, 256>>>(A2, ys, dinv2, db + 128, h2, 1024, 1, np);
    // 12-13. score + topk 1024->512
    k_score<<<128, 256>>>(h2, pw + 128, score, 1024);
    k_topk<<<1, 1024>>>(score, 1024, 512, perm2, vals, (int*)0, nf);
    // 14-15. A3 = perm-ramm(A2) fp32; dinv3
    k_ramm_f32_perm<<<dim3(8, 8), 256>>>(A2, perm2, A3, 512, 1024);
    k_dinv<<<512, 256>>>(A3, 512, dinv3);
    // 16-17. down L3, fused unpool into h2
    k_featw<<<8, 512>>>(h2, dW + 12288, dinv3, nv, nf, perm2, vals, ys, 512);
    k_prop<<<16, 256>>>(A3, ys, dinv3, db + 192, h2, 512, 1, perm2);
    // 18-19. up0 over A2, fused unpool into h1
    k_featw<<<16, 512>>>(h2, uW, dinv2, nv, nf, np, nv, ys, 1024);
    k_prop<<<32, 256>>>(A2, ys, dinv2, ub, h1, 1024, 1, perm1);
    // 20-21. up1 over A1 (CSR), fused unpool into h0
    k_featw<<<32, 512>>>(h1, uW + 4096, dinv1, nv, nf, np, nv, ys, 2048);
    k_prop_sp<<<256, 256>>>(idx1, val1, cnt1, A1_STRIDE, ys, dinv1, ub + 64, h0, 2048, 1, perm0, nv, nf);
    // 22-23. up2 over adj, no relu
    k_featw<<<64, 512>>>(h0, uW + 8192, dinv0, nv, nf, np, nv, ys, 4096);
    k_prop_sp<<<512, 256>>>(idxA, valA, cntA, ADJ_STRIDE, ys, dinv0, ub + 128, u, 4096, 0, np, nv, nf);
    // 24. final
    k_final<<<512, 256>>>(u, fcw, fcb, prob, out, 4096);
}

// round 9
// speedup vs baseline: 2.6104x; 1.1253x over previous
#include <cuda_runtime.h>
#include <cuda_bf16.h>
#include <math.h>

// ---------------- static device scratch (no allocations allowed) -------------
__device__ __nv_bfloat16 g_A1b[2048u*2048u];
__device__ float g_A2[1024u*1024u];
__device__ float g_A3[512u*512u];
__device__ float g_h0[4096*64];
__device__ float g_h1[2048*64];
__device__ float g_h2[1024*64];
__device__ float g_ys[4096*64];
__device__ float g_u[4096*64];
__device__ float g_dinv0[4096];
__device__ float g_dinv1[2048];
__device__ float g_dinv2[1024];
__device__ float g_dinv3[512];
__device__ float g_sums2[1024];
__device__ int   g_perm0[2048];
__device__ int   g_perm1[1024];
__device__ int   g_perm2[512];
__device__ float g_vals[2048];
__device__ float g_score[4096];
__device__ int   g_cntA[4096];
__device__ int   g_cnt1[2048];
__device__ int   g_idxA[4096u*512u];
__device__ float g_valA[4096u*512u];
__device__ int   g_idx1[2048u*2048u];
__device__ float g_val1[2048u*2048u];
__device__ int   g_sel[4096];

#define ADJ_STRIDE 512
#define A1_STRIDE  2048

// ======= single-pass padded CSR build (adj) + dinv ===========================
__global__ void k_fillpad(const float* __restrict__ A, int n, int stride,
                          int* __restrict__ idx, float* __restrict__ val,
                          int* __restrict__ cnt, float* __restrict__ dinvOut) {
    int row = blockIdx.x * 8 + (threadIdx.x >> 5);
    int lane = threadIdx.x & 31;
    const float* a = A + (size_t)row * n;
    int* ridx = idx + (size_t)row * stride;
    float* rval = val + (size_t)row * stride;
    int ptr = 0;
    float fsum = 0.f;
    for (int j0 = 0; j0 < n; j0 += 32) {
        float v = a[j0 + lane];
        fsum += v;
        unsigned msk = __ballot_sync(0xffffffffu, v != 0.f);
        if (v != 0.f) {
            int p = ptr + __popc(msk & ((1u << lane) - 1u));
            if (p < stride) { ridx[p] = j0 + lane; rval[p] = v; }
        }
        ptr += __popc(msk);
    }
    for (int o = 16; o; o >>= 1) fsum += __shfl_xor_sync(0xffffffffu, fsum, o);
    if (lane == 0) {
        cnt[row] = (ptr < stride) ? ptr : stride;
        if (dinvOut != 0) dinvOut[row] = 1.0f / sqrtf(fsum + 2.0f);
    }
}

// ---------------- dinv[i] = 1/sqrt(rowsum(A)+2) (dense) ----------------------
__global__ void k_dinv(const float* __restrict__ A, int n, float* __restrict__ dinv) {
    int row = blockIdx.x;
    const float* a = A + (size_t)row * n;
    float s = 0.f;
    for (int j = threadIdx.x; j < n; j += blockDim.x) s += a[j];
    for (int o = 16; o; o >>= 1) s += __shfl_xor_sync(0xffffffffu, s, o);
    __shared__ float red[8];
    int lane = threadIdx.x & 31;
    int warp = threadIdx.x >> 5;
    if (lane == 0) red[warp] = s;
    __syncthreads();
    if (threadIdx.x == 0) {
        float t = 0.f;
        #pragma unroll
        for (int w = 0; w < 8; w++) t += red[w];
        dinv[row] = 1.0f / sqrtf(t + 2.0f);
    }
}

// --------- ys = d .* ((gather(X)) @ W); d from dinvIn or rsqrt(sums+2) -------
__global__ void __launch_bounds__(512) k_featw(const float* __restrict__ X,
                        const float* __restrict__ W,
                        const float* __restrict__ dinvIn, const float* __restrict__ sums,
                        float* __restrict__ dinvOut,
                        const int* __restrict__ perm, const float* __restrict__ vals,
                        float* __restrict__ ys, int n) {
    __shared__ float Ws[64][64];
    __shared__ float Xs[64][65];
    int tid = threadIdx.x; // 512
    int rowb = blockIdx.x * 64;
    const float4* W4 = (const float4*)W;
    float4* Ws4 = (float4*)&Ws[0][0];
    for (int i = tid; i < 1024; i += 512) Ws4[i] = W4[i];
    for (int i = tid; i < 1024; i += 512) {
        int r = i >> 4;
        int c4 = (i & 15) << 2;
        int rs = rowb + r;
        const float* src;
        float scale = 1.f;
        if (perm != 0) { src = X + (size_t)perm[rs] * 64; scale = vals[rs]; }
        else           { src = X + (size_t)rs * 64; }
        float4 v = *(const float4*)(src + c4);
        Xs[r][c4+0] = v.x * scale;
        Xs[r][c4+1] = v.y * scale;
        Xs[r][c4+2] = v.z * scale;
        Xs[r][c4+3] = v.w * scale;
    }
    __syncthreads();
    int tx = tid & 15;
    int ty = tid >> 4;
    float4 acc0 = make_float4(0.f, 0.f, 0.f, 0.f);
    float4 acc1 = make_float4(0.f, 0.f, 0.f, 0.f);
    #pragma unroll 8
    for (int k = 0; k < 64; k++) {
        float4 b = *(float4*)&Ws[k][tx * 4];
        float a0 = Xs[ty*2+0][k];
        float a1 = Xs[ty*2+1][k];
        acc0.x += a0*b.x; acc0.y += a0*b.y; acc0.z += a0*b.z; acc0.w += a0*b.w;
        acc1.x += a1*b.x; acc1.y += a1*b.y; acc1.z += a1*b.z; acc1.w += a1*b.w;
    }
    int r0 = rowb + ty*2;
    float d0, d1;
    if (sums != 0) {
        d0 = 1.0f / sqrtf(sums[r0] + 2.0f);
        d1 = 1.0f / sqrtf(sums[r0 + 1] + 2.0f);
    } else {
        d0 = dinvIn[r0];
        d1 = dinvIn[r0 + 1];
    }
    if (dinvOut != 0 && tx == 0) { dinvOut[r0] = d0; dinvOut[r0 + 1] = d1; }
    float4 o0 = make_float4(acc0.x*d0, acc0.y*d0, acc0.z*d0, acc0.w*d0);
    float4 o1 = make_float4(acc1.x*d1, acc1.y*d1, acc1.z*d1, acc1.w*d1);
    *(float4*)(ys + (size_t)r0 * 64 + tx * 4) = o0;
    *(float4*)(ys + (size_t)(r0 + 1) * 64 + tx * 4) = o1;
}

// ---- padded sparse prop (+ optional fused score, optional scatter-out) ------
__global__ void k_prop_sp(const int* __restrict__ idx, const float* __restrict__ val,
                          const int* __restrict__ cnt, int stride,
                          const float* __restrict__ ys,
                          const float* __restrict__ dinv, const float* __restrict__ bias,
                          float* __restrict__ h, int n, int relu,
                          const int* __restrict__ permOut,
                          const float* __restrict__ pw, float* __restrict__ scoreOut) {
    int row = blockIdx.x * 8 + (threadIdx.x >> 5);
    int lane = threadIdx.x & 31;
    if (row >= n) return;
    const int* ridx = idx + (size_t)row * stride;
    const float* rval = val + (size_t)row * stride;
    int e = cnt[row];
    float a0 = 0.f;
    float a1 = 0.f;
    for (int m = 0; m < e; m++) {
        int j = ridx[m];
        float w = rval[m];
        a0 += w * ys[(size_t)j * 64 + lane];
        a1 += w * ys[(size_t)j * 64 + 32 + lane];
    }
    float d = dinv[row];
    float v0 = d * a0 + 2.f * d * ys[(size_t)row * 64 + lane] + bias[lane];
    float v1 = d * a1 + 2.f * d * ys[(size_t)row * 64 + 32 + lane] + bias[32 + lane];
    if (relu) { v0 = fmaxf(v0, 0.f); v1 = fmaxf(v1, 0.f); }
    if (permOut != 0) {
        float* dst = h + (size_t)permOut[row] * 64;
        dst[lane] += v0;
        dst[32 + lane] += v1;
    } else {
        h[(size_t)row * 64 + lane] = v0;
        h[(size_t)row * 64 + 32 + lane] = v1;
    }
    if (scoreOut != 0) {
        float pl = pw[lane];
        float ph = pw[32 + lane];
        float pn = pl*pl + ph*ph;
        float dd = v0 * pl + v1 * ph;
        for (int o = 16; o; o >>= 1) {
            dd += __shfl_xor_sync(0xffffffffu, dd, o);
            pn += __shfl_xor_sync(0xffffffffu, pn, o);
        }
        if (lane == 0) scoreOut[row] = tanhf(dd * (1.0f / sqrtf(pn)));
    }
}

// ---------------- dense prop -------------------------------------------------
__global__ void k_prop(const float* __restrict__ A, const float* __restrict__ ys,
                       const float* __restrict__ dinv, const float* __restrict__ bias,
                       float* __restrict__ hout, int n, int relu,
                       const int* __restrict__ permOut) {
    __shared__ float sA[32][33];
    __shared__ float sB[32][64];
    int tid = threadIdx.x; // 256
    int tx = tid & 15;
    int ty = tid >> 4;
    int rowb = blockIdx.x * 32;
    float acc[2][4] = {{0.f,0.f,0.f,0.f},{0.f,0.f,0.f,0.f}};
    for (int kb = 0; kb < n; kb += 32) {
        int r0 = tid >> 3;
        int c0 = (tid & 7) * 4;
        float4 v = *(const float4*)(A + (size_t)(rowb + r0) * n + kb + c0);
        sA[r0][c0] = v.x; sA[r0][c0+1] = v.y; sA[r0][c0+2] = v.z; sA[r0][c0+3] = v.w;
        for (int q = tid; q < 512; q += 256) {
            int r = q >> 4;
            int c4 = (q & 15) * 4;
            *(float4*)&sB[r][c4] = *(const float4*)(ys + (size_t)(kb + r) * 64 + c4);
        }
        __syncthreads();
        #pragma unroll
        for (int kk = 0; kk < 32; kk++) {
            float a0 = sA[ty*2+0][kk];
            float a1 = sA[ty*2+1][kk];
            float4 b = *(float4*)&sB[kk][tx*4];
            acc[0][0] += a0*b.x; acc[0][1] += a0*b.y; acc[0][2] += a0*b.z; acc[0][3] += a0*b.w;
            acc[1][0] += a1*b.x; acc[1][1] += a1*b.y; acc[1][2] += a1*b.z; acc[1][3] += a1*b.w;
        }
        __syncthreads();
    }
    #pragma unroll
    for (int i = 0; i < 2; i++) {
        int r = rowb + ty*2 + i;
        float d = dinv[r];
        int orow = (permOut != 0) ? permOut[r] : r;
        #pragma unroll
        for (int j = 0; j < 4; j++) {
            int c = tx*4 + j;
            float v = d*acc[i][j] + 2.f*d*ys[(size_t)r*64 + c] + bias[c];
            if (relu) v = fmaxf(v, 0.f);
            if (permOut != 0) hout[(size_t)orow*64 + c] += v;
            else              hout[(size_t)orow*64 + c] = v;
        }
    }
}

// ---------------- standalone score (level 2 only) ----------------------------
__global__ void k_score(const float* __restrict__ h, const float* __restrict__ p,
                        float* __restrict__ score, int n) {
    int gw = (blockIdx.x * blockDim.x + threadIdx.x) >> 5;
    int lane = threadIdx.x & 31;
    if (gw >= n) return;
    float pl = p[lane];
    float ph = p[32 + lane];
    float pn = pl*pl + ph*ph;
    float d = h[(size_t)gw*64 + lane] * pl + h[(size_t)gw*64 + 32 + lane] * ph;
    for (int o = 16; o; o >>= 1) {
        d  += __shfl_xor_sync(0xffffffffu, d, o);
        pn += __shfl_xor_sync(0xffffffffu, pn, o);
    }
    if (lane == 0) score[gw] = tanhf(d * (1.0f / sqrtf(pn)));
}

// -------- rank-select topk: rank(i) = #{j: key_j > key_i}; exact total order --
// key = (monotone(score) << 32) | ~i  -> identical ordering to bitonic sort
// (score desc, idx asc). Bijection rank: [0,n) -> direct scatter, no sort.
__global__ void __launch_bounds__(256) k_rank(const float* __restrict__ score,
                      int n, int k,
                      int* __restrict__ perm, float* __restrict__ vals,
                      int* __restrict__ sel, float* __restrict__ zeroBuf) {
    __shared__ unsigned long long tile[2048];
    int tid = threadIdx.x;  // 256
    int elem = blockIdx.x * 64 + (tid >> 2);
    int part = tid & 3;
    float myscore = score[elem];
    unsigned mb = __float_as_uint(myscore);
    mb = (mb & 0x80000000u) ? (mb ^ 0xFFFFFFFFu) : (mb ^ 0x80000000u);
    unsigned long long my = ((unsigned long long)mb << 32) | (unsigned)(~elem);
    int cnt = 0;
    for (int t0 = 0; t0 < n; t0 += 2048) {
        int tl = n - t0;
        if (tl > 2048) tl = 2048;
        __syncthreads();
        for (int i = tid; i < tl; i += 256) {
            unsigned b = __float_as_uint(score[t0 + i]);
            b = (b & 0x80000000u) ? (b ^ 0xFFFFFFFFu) : (b ^ 0x80000000u);
            tile[i] = ((unsigned long long)b << 32) | (unsigned)(~(t0 + i));
        }
        __syncthreads();
        for (int i = part; i < tl; i += 4) cnt += (tile[i] > my) ? 1 : 0;
    }
    cnt += __shfl_xor_sync(0xffffffffu, cnt, 1);
    cnt += __shfl_xor_sync(0xffffffffu, cnt, 2);
    if (part == 0) {
        if (cnt < k) {
            perm[cnt] = elem;
            vals[cnt] = myscore;
            if (sel != 0) sel[elem] = cnt;
            if (zeroBuf != 0) zeroBuf[cnt] = 0.f;
        } else {
            if (sel != 0) sel[elem] = -1;
        }
    }
}

// ------- augment row builder: A1 bf16 dense row + CSR row + dinv1 ------------
// A1[a][b] = #{ j : j in N_sl(perm0[a]) and j in N_sl(perm0[b]) }, diag = 0
__global__ void k_augrow(const int* __restrict__ idxA, const int* __restrict__ cntA,
                         const int* __restrict__ sel, const int* __restrict__ perm0,
                         __nv_bfloat16* __restrict__ A1b,
                         int* __restrict__ idx1, float* __restrict__ val1,
                         int* __restrict__ cnt1, float* __restrict__ dinv1) {
    __shared__ unsigned counts[2048];
    __shared__ int jlist[528];
    int a = blockIdx.x;
    int pa = perm0[a];
    int tid = threadIdx.x; // 256
    for (int i = tid; i < 2048; i += 256) counts[i] = 0u;
    int na = cntA[pa];
    for (int i = tid; i < na; i += 256) jlist[i] = idxA[(size_t)pa * ADJ_STRIDE + i];
    if (tid == 0) jlist[na] = pa;
    __syncthreads();
    int warp = tid >> 5;
    int lane = tid & 31;
    for (int ji = warp; ji < na + 1; ji += 8) {
        int j = jlist[ji];
        int nj = cntA[j];
        const int* rj = idxA + (size_t)j * ADJ_STRIDE;
        for (int m = lane; m < nj + 1; m += 32) {
            int uu = (m < nj) ? rj[m] : j;
            int s = sel[uu];
            if (s >= 0) atomicAdd(&counts[s], 1u);
        }
    }
    __syncthreads();
    if (tid == 0) counts[a] = 0u; // remove self loop
    __syncthreads();
    // dense bf16 row
    unsigned* dst = (unsigned*)(A1b + (size_t)a * 2048);
    for (int i = tid; i < 1024; i += 256) {
        __nv_bfloat162 pr;
        pr.x = __float2bfloat16((float)counts[2*i]);
        pr.y = __float2bfloat16((float)counts[2*i + 1]);
        dst[i] = *(unsigned*)&pr;
    }
    // CSR row + dinv by warp 0
    if (warp == 0) {
        int ptr = 0;
        float fsum = 0.f;
        int* ridx = idx1 + (size_t)a * A1_STRIDE;
        float* rval = val1 + (size_t)a * A1_STRIDE;
        for (int j0 = 0; j0 < 2048; j0 += 32) {
            unsigned c = counts[j0 + lane];
            fsum += (float)c;
            unsigned msk = __ballot_sync(0xffffffffu, c != 0u);
            if (c != 0u) {
                int p = ptr + __popc(msk & ((1u << lane) - 1u));
                ridx[p] = j0 + lane;
                rval[p] = (float)c;
            }
            ptr += __popc(msk);
        }
        for (int o = 16; o; o >>= 1) fsum += __shfl_xor_sync(0xffffffffu, fsum, o);
        if (lane == 0) {
            cnt1[a] = ptr;
            dinv1[a] = 1.0f / sqrtf(fsum + 2.0f);
        }
    }
}

// -- bf16 mma ramm with perm rows: C = dot(A[pa],A[pb]) + 2A[pa][pb]; +rowsums
__global__ void __launch_bounds__(128) k_ramm_mma_perm(const __nv_bfloat16* __restrict__ Ab,
        const int* __restrict__ perm, float* __restrict__ C, float* __restrict__ sums,
        int k, int m) {
    int w = threadIdx.x >> 5;
    int l = threadIdx.x & 31;
    int rb = blockIdx.x * 64 + w * 16;
    int cb = blockIdx.y * 64;
    int lr = l >> 2;
    int lc = l & 3;
    int ra0 = perm[rb + lr];
    int ra1 = perm[rb + lr + 8];
    int rbv[8];
    #pragma unroll
    for (int t = 0; t < 8; t++) rbv[t] = perm[cb + t*8 + lr];
    float acc[8][4];
    #pragma unroll
    for (int t = 0; t < 8; t++) {
        #pragma unroll
        for (int j = 0; j < 4; j++) acc[t][j] = 0.f;
    }
    const unsigned* A0 = (const unsigned*)(Ab + (size_t)ra0 * m) + lc;
    const unsigned* A1r = (const unsigned*)(Ab + (size_t)ra1 * m) + lc;
    for (int kb = 0; kb < m; kb += 16) {
        int kw = kb >> 1;
        unsigned a0 = A0[kw];
        unsigned a1 = A1r[kw];
        unsigned a2 = A0[kw + 4];
        unsigned a3 = A1r[kw + 4];
        #pragma unroll
        for (int t = 0; t < 8; t++) {
            const unsigned* Bp = (const unsigned*)(Ab + (size_t)rbv[t] * m) + lc;
            unsigned b0 = Bp[kw];
            unsigned b1 = Bp[kw + 4];
            asm volatile(
                "mma.sync.aligned.m16n8k16.row.col.f32.bf16.bf16.f32 "
                "{%0,%1,%2,%3}, {%4,%5,%6,%7}, {%8,%9}, {%0,%1,%2,%3};"
                : "+f"(acc[t][0]), "+f"(acc[t][1]), "+f"(acc[t][2]), "+f"(acc[t][3])
                : "r"(a0), "r"(a1), "r"(a2), "r"(a3), "r"(b0), "r"(b1));
        }
    }
    int row0 = rb + lr;
    int row1 = rb + lr + 8;
    float rs0 = 0.f;
    float rs1 = 0.f;
    #pragma unroll
    for (int t = 0; t < 8; t++) {
        int c0 = cb + t * 8 + lc * 2;
        int c1 = c0 + 1;
        int pc0 = perm[c0];
        int pc1 = perm[c1];
        float v00 = (row0 == c0) ? 0.f : acc[t][0] + 2.f * __bfloat162float(Ab[(size_t)ra0 * m + pc0]);
        float v01 = (row0 == c1) ? 0.f : acc[t][1] + 2.f * __bfloat162float(Ab[(size_t)ra0 * m + pc1]);
        float v10 = (row1 == c0) ? 0.f : acc[t][2] + 2.f * __bfloat162float(Ab[(size_t)ra1 * m + pc0]);
        float v11 = (row1 == c1) ? 0.f : acc[t][3] + 2.f * __bfloat162float(Ab[(size_t)ra1 * m + pc1]);
        *(float2*)&C[(size_t)row0 * k + c0] = make_float2(v00, v01);
        *(float2*)&C[(size_t)row1 * k + c0] = make_float2(v10, v11);
        rs0 += v00 + v01;
        rs1 += v10 + v11;
    }
    if (sums != 0) {
        atomicAdd(&sums[row0], rs0);  // integer-valued: exact, order-free
        atomicAdd(&sums[row1], rs1);
    }
}

// -- fp32 SIMT ramm with perm rows (level 2): C = dot + 2*A[pa][pb], diag 0 ---
__global__ void k_ramm_f32_perm(const float* __restrict__ A, const int* __restrict__ perm,
                                float* __restrict__ C, int k, int m) {
    __shared__ float sA[64][33];
    __shared__ float sB[64][33];
    __shared__ int prA[64];
    __shared__ int prB[64];
    int tid = threadIdx.x; // 256
    int tx = tid & 15;
    int ty = tid >> 4;
    int rb = blockIdx.x * 64;
    int cb = blockIdx.y * 64;
    if (tid < 64) prA[tid] = perm[rb + tid];
    else if (tid < 128) prB[tid - 64] = perm[cb + tid - 64];
    __syncthreads();
    float acc[4][4];
    #pragma unroll
    for (int i = 0; i < 4; i++) {
        #pragma unroll
        for (int j = 0; j < 4; j++) acc[i][j] = 0.f;
    }
    for (int kb = 0; kb < m; kb += 32) {
        for (int q = tid; q < 512; q += 256) {
            int r = q >> 3;
            int c4 = (q & 7) * 4;
            float4 v = *(const float4*)(A + (size_t)prA[r] * m + kb + c4);
            sA[r][c4] = v.x; sA[r][c4+1] = v.y; sA[r][c4+2] = v.z; sA[r][c4+3] = v.w;
            float4 u = *(const float4*)(A + (size_t)prB[r] * m + kb + c4);
            sB[r][c4] = u.x; sB[r][c4+1] = u.y; sB[r][c4+2] = u.z; sB[r][c4+3] = u.w;
        }
        __syncthreads();
        #pragma unroll
        for (int w = 0; w < 32; w++) {
            float a0 = sA[ty*4+0][w];
            float a1 = sA[ty*4+1][w];
            float a2 = sA[ty*4+2][w];
            float a3 = sA[ty*4+3][w];
            float b0 = sB[tx*4+0][w];
            float b1 = sB[tx*4+1][w];
            float b2 = sB[tx*4+2][w];
            float b3 = sB[tx*4+3][w];
            acc[0][0] += a0*b0; acc[0][1] += a0*b1; acc[0][2] += a0*b2; acc[0][3] += a0*b3;
            acc[1][0] += a1*b0; acc[1][1] += a1*b1; acc[1][2] += a1*b2; acc[1][3] += a1*b3;
            acc[2][0] += a2*b0; acc[2][1] += a2*b1; acc[2][2] += a2*b2; acc[2][3] += a2*b3;
            acc[3][0] += a3*b0; acc[3][1] += a3*b1; acc[3][2] += a3*b2; acc[3][3] += a3*b3;
        }
        __syncthreads();
    }
    #pragma unroll
    for (int i = 0; i < 4; i++) {
        int gr = rb + ty*4 + i;
        int pr = prA[ty*4 + i];
        #pragma unroll
        for (int j = 0; j < 4; j++) {
            int gc = cb + tx*4 + j;
            float v = acc[i][j] + 2.f * A[(size_t)pr * m + prB[tx*4 + j]];
            C[(size_t)gr * k + gc] = (gr == gc) ? 0.f : v;
        }
    }
}

// ---------------- final: relu, dropout(0), fc --------------------------------
__global__ void k_final(const float* __restrict__ g, const float* __restrict__ fcw,
                        const float* __restrict__ fcb, const float* __restrict__ prob,
                        float* __restrict__ out, int n) {
    int gw = (blockIdx.x * blockDim.x + threadIdx.x) >> 5;
    int lane = threadIdx.x & 31;
    if (gw >= n) return;
    float v = fmaxf(g[(size_t)gw*64 + lane], 0.f)      * fcw[lane]
            + fmaxf(g[(size_t)gw*64 + 32 + lane], 0.f) * fcw[32 + lane];
    for (int o = 16; o; o >>= 1) v += __shfl_xor_sync(0xffffffffu, v, o);
    if (lane == 0) out[gw] = v / (1.f - prob[0]) + fcb[0];
}

// =============================================================================
extern "C" void kernel_launch(void* const* d_in, const int* in_sizes, int n_in,
                              void* d_out, int out_size) {
    (void)in_sizes;
    (void)n_in;
    (void)out_size;
    const float* x    = (const float*)d_in[0];
    const float* adj  = (const float*)d_in[1];
    const float* prob = (const float*)d_in[2];
    const float* dW   = (const float*)d_in[3];
    const float* db   = (const float*)d_in[4];
    const float* pw   = (const float*)d_in[5];
    const float* uW   = (const float*)d_in[6];
    const float* ub   = (const float*)d_in[7];
    const float* fcw  = (const float*)d_in[8];
    const float* fcb  = (const float*)d_in[9];
    float* out = (float*)d_out;

    void* pv;
    cudaGetSymbolAddress(&pv, g_A1b);   __nv_bfloat16* A1b = (__nv_bfloat16*)pv;
    cudaGetSymbolAddress(&pv, g_A2);    float* A2 = (float*)pv;
    cudaGetSymbolAddress(&pv, g_A3);    float* A3 = (float*)pv;
    cudaGetSymbolAddress(&pv, g_h0);    float* h0 = (float*)pv;
    cudaGetSymbolAddress(&pv, g_h1);    float* h1 = (float*)pv;
    cudaGetSymbolAddress(&pv, g_h2);    float* h2 = (float*)pv;
    cudaGetSymbolAddress(&pv, g_ys);    float* ys = (float*)pv;
    cudaGetSymbolAddress(&pv, g_u);     float* u  = (float*)pv;
    cudaGetSymbolAddress(&pv, g_dinv0); float* dinv0 = (float*)pv;
    cudaGetSymbolAddress(&pv, g_dinv1); float* dinv1 = (float*)pv;
    cudaGetSymbolAddress(&pv, g_dinv2); float* dinv2 = (float*)pv;
    cudaGetSymbolAddress(&pv, g_dinv3); float* dinv3 = (float*)pv;
    cudaGetSymbolAddress(&pv, g_sums2); float* sums2 = (float*)pv;
    cudaGetSymbolAddress(&pv, g_perm0); int* perm0 = (int*)pv;
    cudaGetSymbolAddress(&pv, g_perm1); int* perm1 = (int*)pv;
    cudaGetSymbolAddress(&pv, g_perm2); int* perm2 = (int*)pv;
    cudaGetSymbolAddress(&pv, g_vals);  float* vals = (float*)pv;
    cudaGetSymbolAddress(&pv, g_score); float* score = (float*)pv;
    cudaGetSymbolAddress(&pv, g_cntA);  int* cntA = (int*)pv;
    cudaGetSymbolAddress(&pv, g_cnt1);  int* cnt1 = (int*)pv;
    cudaGetSymbolAddress(&pv, g_idxA);  int* idxA = (int*)pv;
    cudaGetSymbolAddress(&pv, g_valA);  float* valA = (float*)pv;
    cudaGetSymbolAddress(&pv, g_idx1);  int* idx1 = (int*)pv;
    cudaGetSymbolAddress(&pv, g_val1);  float* val1 = (float*)pv;
    cudaGetSymbolAddress(&pv, g_sel);   int* sel  = (int*)pv;

    const int* np = (const int*)0;
    const float* nv = (const float*)0;
    float* nf = (float*)0;

    // 1. CSR(adj) + dinv0
    k_fillpad<<<512, 256>>>(adj, 4096, ADJ_STRIDE, idxA, valA, cntA, dinv0);
    // 2-3. down L0 + fused score
    k_featw<<<64, 512>>>(x, dW, dinv0, nv, nf, np, nv, ys, 4096);
    k_prop_sp<<<512, 256>>>(idxA, valA, cntA, ADJ_STRIDE, ys, dinv0, db, h0, 4096, 1, np, pw, score);
    // 4. rank-select 4096->2048 (writes sel)
    k_rank<<<64, 256>>>(score, 4096, 2048, perm0, vals, sel, nf);
    // 5. augment: A1 bf16 dense + CSR1 + dinv1
    k_augrow<<<2048, 256>>>(idxA, cntA, sel, perm0, A1b, idx1, val1, cnt1, dinv1);
    // 6-7. down L1 + fused score
    k_featw<<<32, 512>>>(h0, dW + 4096, dinv1, nv, nf, perm0, vals, ys, 2048);
    k_prop_sp<<<256, 256>>>(idx1, val1, cnt1, A1_STRIDE, ys, dinv1, db + 64, h1, 2048, 1, np, pw + 64, score);
    // 8. rank-select 2048->1024 (zeroes sums2)
    k_rank<<<32, 256>>>(score, 2048, 1024, perm1, vals, (int*)0, sums2);
    // 9. A2 = perm-ramm(A1) via mma, + integer-exact rowsums
    k_ramm_mma_perm<<<dim3(16, 16), 128>>>(A1b, perm1, A2, sums2, 1024, 2048);
    // 10-11. down L2 (dinv2 from sums2, written for later reuse)
    k_featw<<<16, 512>>>(h1, dW + 8192, nv, sums2, dinv2, perm1, vals, ys, 1024);
    k_prop<<<32, 256>>>(A2, ys, dinv2, db + 128, h2, 1024, 1, np);
    // 12-13. score + rank-select 1024->512
    k_score<<<128, 256>>>(h2, pw + 128, score, 1024);
    k_rank<<<16, 256>>>(score, 1024, 512, perm2, vals, (int*)0, nf);
    // 14-15. A3 = perm-ramm(A2) fp32; dinv3
    k_ramm_f32_perm<<<dim3(8, 8), 256>>>(A2, perm2, A3, 512, 1024);
    k_dinv<<<512, 256>>>(A3, 512, dinv3);
    // 16-17. down L3, fused unpool into h2
    k_featw<<<8, 512>>>(h2, dW + 12288, dinv3, nv, nf, perm2, vals, ys, 512);
    k_prop<<<16, 256>>>(A3, ys, dinv3, db + 192, h2, 512, 1, perm2);
    // 18-19. up0 over A2, fused unpool into h1
    k_featw<<<16, 512>>>(h2, uW, dinv2, nv, nf, np, nv, ys, 1024);
    k_prop<<<32, 256>>>(A2, ys, dinv2, ub, h1, 1024, 1, perm1);
    // 20-21. up1 over A1 (CSR), fused unpool into h0
    k_featw<<<32, 512>>>(h1, uW + 4096, dinv1, nv, nf, np, nv, ys, 2048);
    k_prop_sp<<<256, 256>>>(idx1, val1, cnt1, A1_STRIDE, ys, dinv1, ub + 64, h0, 2048, 1, perm0, nv, nf);
    // 22-23. up2 over adj, no relu
    k_featw<<<64, 512>>>(h0, uW + 8192, dinv0, nv, nf, np, nv, ys, 4096);
    k_prop_sp<<<512, 256>>>(idxA, valA, cntA, ADJ_STRIDE, ys, dinv0, ub + 128, u, 4096, 0, np, nv, nf);
    // 24. final
    k_final<<<512, 256>>>(u, fcw, fcb, prob, out, 4096);
}